// round 2
// baseline (speedup 1.0000x reference)
#include <cuda_runtime.h>
#include <math.h>

// Problem constants
#define BB   16
#define CC   1024
#define HH   32
#define WW   32
#define NE   256
#define NPIX (BB*HH*WW)          // 16384
#define OUT_ELEMS (BB*CC*HH*WW)  // 16777216
#define LOSS_OFF  OUT_ELEMS
#define PERP_OFF  (OUT_ELEMS+1)
#define IDX_OFF   (OUT_ELEMS+2)

// Scratch (no cudaMalloc allowed)
__device__ float g_code_out[NE*CC];   // emb @ conv_w^T + b   (4 MB)
__device__ float g_ee2[NE];           // |e_j|^2
__device__ int   g_idx[NPIX];
__device__ int   g_counts[NE];
__device__ float g_loss_sum;

// ---------------------------------------------------------------------------
// Kernel 0: |e_j|^2 per code + reset accumulators (must run first each launch)
// ---------------------------------------------------------------------------
__global__ void k_ee2_reset(const float* __restrict__ emb) {
    int j = blockIdx.x;          // 256 blocks
    int t = threadIdx.x;         // 256 threads
    float s = 0.f;
    for (int c = t; c < CC; c += 256) {
        float v = emb[j*CC + c];
        s += v*v;
    }
    __shared__ float red[256];
    red[t] = s; __syncthreads();
    for (int st = 128; st > 0; st >>= 1) {
        if (t < st) red[t] += red[t+st];
        __syncthreads();
    }
    if (t == 0) {
        g_ee2[j] = red[0];
        g_counts[j] = 0;
        if (j == 0) g_loss_sum = 0.f;
    }
}

// ---------------------------------------------------------------------------
// Kernel 1: code_out[j][o] = sum_c emb[j][c]*conv_w[o][c] + conv_b[o]
// 64x64 tiles, 256 threads, 4x4 microtile, K-chunks of 16.
// ---------------------------------------------------------------------------
__global__ void __launch_bounds__(256) k_codeout(
    const float* __restrict__ emb, const float* __restrict__ w,
    const float* __restrict__ bias)
{
    __shared__ float es[16][64];
    __shared__ float ws[16][64];
    int t  = threadIdx.x;
    int o0 = blockIdx.x * 64;    // 16 tiles over O=1024
    int j0 = blockIdx.y * 64;    // 4  tiles over J=256
    int rl  = t & 63, grp = t >> 6;   // load mapping
    int tol = t & 15, tjl = t >> 4;   // compute mapping (16x16 threads)
    float acc[4][4] = {};

    for (int k0 = 0; k0 < CC; k0 += 16) {
        float4 fe = *(const float4*)&emb[(size_t)(j0+rl)*CC + k0 + grp*4];
        float4 fw = *(const float4*)&w  [(size_t)(o0+rl)*CC + k0 + grp*4];
        es[grp*4+0][rl]=fe.x; es[grp*4+1][rl]=fe.y; es[grp*4+2][rl]=fe.z; es[grp*4+3][rl]=fe.w;
        ws[grp*4+0][rl]=fw.x; ws[grp*4+1][rl]=fw.y; ws[grp*4+2][rl]=fw.z; ws[grp*4+3][rl]=fw.w;
        __syncthreads();
        #pragma unroll
        for (int kk = 0; kk < 16; kk++) {
            float er[4], wr[4];
            #pragma unroll
            for (int i = 0; i < 4; i++) { er[i] = es[kk][tjl*4+i]; wr[i] = ws[kk][tol*4+i]; }
            #pragma unroll
            for (int jy = 0; jy < 4; jy++)
                #pragma unroll
                for (int ox = 0; ox < 4; ox++)
                    acc[jy][ox] = fmaf(er[jy], wr[ox], acc[jy][ox]);
        }
        __syncthreads();
    }
    #pragma unroll
    for (int jy = 0; jy < 4; jy++)
        #pragma unroll
        for (int ox = 0; ox < 4; ox++) {
            int j = j0 + tjl*4 + jy;
            int o = o0 + tol*4 + ox;
            g_code_out[(size_t)j*CC + o] = acc[jy][ox] + bias[o];
        }
}

// ---------------------------------------------------------------------------
// Kernel 2: per-pixel argmin_j (|e_j|^2 - 2 z.e_j). One block per (b,h) row
// of 32 pixels, all 256 codes. fp32 FFMA, smem-tiled, 4 pix x 8 codes / thread.
// ---------------------------------------------------------------------------
__global__ void __launch_bounds__(256) k_argmin(
    const float* __restrict__ z, const float* __restrict__ emb,
    float* __restrict__ out)
{
    int bh = blockIdx.x;              // 512 blocks
    int b = bh >> 5, h = bh & 31;
    __shared__ float z_s[16][32];
    __shared__ float e_s[16][256];
    __shared__ unsigned long long sKey[32];
    int t  = threadIdx.x;
    int pl = t >> 5;                  // pixel group 0..7 -> pixels pl*4..pl*4+3
    int cl = t & 31;                  // code lane -> codes cl+32g

    if (t < 32) sKey[t] = ~0ull;

    float acc[4][8];
    #pragma unroll
    for (int i = 0; i < 4; i++)
        #pragma unroll
        for (int g = 0; g < 8; g++) acc[i][g] = 0.f;

    const float* zb = z + (size_t)b*(CC*HH*WW) + h*WW;  // + c*1024 + w

    for (int k0 = 0; k0 < CC; k0 += 16) {
        // z chunk: 16 k x 32 w (512 floats, 2/thread, coalesced)
        {
            int i0 = t, i1 = t + 256;
            z_s[i0>>5][i0&31] = zb[(size_t)(k0 + (i0>>5))*(HH*WW) + (i0&31)];
            z_s[i1>>5][i1&31] = zb[(size_t)(k0 + (i1>>5))*(HH*WW) + (i1&31)];
        }
        // emb chunk: 256 codes x 16 k, thread t = code t, 4x float4
        {
            const float4* ep = (const float4*)&emb[(size_t)t*CC + k0];
            #pragma unroll
            for (int q = 0; q < 4; q++) {
                float4 f = ep[q];
                e_s[q*4+0][t]=f.x; e_s[q*4+1][t]=f.y; e_s[q*4+2][t]=f.z; e_s[q*4+3][t]=f.w;
            }
        }
        __syncthreads();
        #pragma unroll
        for (int kk = 0; kk < 16; kk++) {
            float zr[4];
            #pragma unroll
            for (int i = 0; i < 4; i++) zr[i] = z_s[kk][pl*4+i];   // broadcast
            #pragma unroll
            for (int g = 0; g < 8; g++) {
                float er = e_s[kk][cl + 32*g];                     // conflict-free
                #pragma unroll
                for (int i = 0; i < 4; i++)
                    acc[i][g] = fmaf(zr[i], er, acc[i][g]);
            }
        }
        __syncthreads();
    }

    float ee[8];
    #pragma unroll
    for (int g = 0; g < 8; g++) ee[g] = g_ee2[cl + 32*g];

    #pragma unroll
    for (int i = 0; i < 4; i++) {
        unsigned long long bk = ~0ull;
        #pragma unroll
        for (int g = 0; g < 8; g++) {
            int j = cl + 32*g;
            float s = ee[g] - 2.f*acc[i][g];
            unsigned u = __float_as_uint(s);
            u = (u & 0x80000000u) ? ~u : (u | 0x80000000u);   // order-preserving map
            unsigned long long key = ((unsigned long long)u << 32) | (unsigned)j;
            bk = (key < bk) ? key : bk;                        // ties -> lower j
        }
        atomicMin(&sKey[pl*4 + i], bk);
    }
    __syncthreads();
    if (t < 32) {
        int j = (int)(sKey[t] & 0xFFFFFFFFu);
        int n = bh*32 + t;            // pixel index b*1024 + h*32 + w
        g_idx[n] = j;
        atomicAdd(&g_counts[j], 1);
        out[IDX_OFF + n] = (float)j;
    }
}

// ---------------------------------------------------------------------------
// Kernel 3: out[b,o,h,w] = code_out[idx][o]; loss partial = sum (emb[idx]-z)^2
// One block per (b,h) row.
// ---------------------------------------------------------------------------
__global__ void __launch_bounds__(256) k_scatter(
    const float* __restrict__ z, const float* __restrict__ emb,
    float* __restrict__ out)
{
    int bh = blockIdx.x;
    int b = bh >> 5, h = bh & 31;
    __shared__ int idx_s[32];
    int t = threadIdx.x;
    if (t < 32) idx_s[t] = g_idx[bh*32 + t];
    __syncthreads();

    size_t base = (size_t)b*(CC*HH*WW) + h*WW;
    float lsum = 0.f;
    for (int i = t; i < CC*32; i += 256) {
        int c = i >> 5, w = i & 31;
        int j = idx_s[w];
        float ev = emb[(size_t)j*CC + c];
        float zv = z[base + (size_t)c*(HH*WW) + w];
        float d  = ev - zv;
        lsum = fmaf(d, d, lsum);
        out[base + (size_t)c*(HH*WW) + w] = g_code_out[(size_t)j*CC + c];
    }
    __shared__ float red[256];
    red[t] = lsum; __syncthreads();
    for (int st = 128; st > 0; st >>= 1) {
        if (t < st) red[t] += red[t+st];
        __syncthreads();
    }
    if (t == 0) atomicAdd(&g_loss_sum, red[0]);
}

// ---------------------------------------------------------------------------
// Kernel 4: finalize loss + perplexity
// ---------------------------------------------------------------------------
__global__ void k_finalize(float* __restrict__ out) {
    int t = threadIdx.x;   // 256 threads, 1 block
    float em = (float)g_counts[t] / (float)NPIX;
    float term = em * logf(em + 1e-10f);
    __shared__ float red[256];
    red[t] = term; __syncthreads();
    for (int st = 128; st > 0; st >>= 1) {
        if (t < st) red[t] += red[t+st];
        __syncthreads();
    }
    if (t == 0) {
        out[LOSS_OFF] = 1.25f * g_loss_sum / (float)OUT_ELEMS;  // (1+BETA)*mse
        out[PERP_OFF] = expf(-red[0]);
    }
}

// ---------------------------------------------------------------------------
extern "C" void kernel_launch(void* const* d_in, const int* in_sizes, int n_in,
                              void* d_out, int out_size) {
    const float* z      = (const float*)d_in[0];
    const float* emb    = (const float*)d_in[1];
    const float* conv_w = (const float*)d_in[2];
    const float* conv_b = (const float*)d_in[3];
    float* out = (float*)d_out;

    k_ee2_reset<<<NE, 256>>>(emb);
    k_codeout<<<dim3(CC/64, NE/64), 256>>>(emb, conv_w, conv_b);
    k_argmin<<<BB*HH, 256>>>(z, emb, out);
    k_scatter<<<BB*HH, 256>>>(z, emb, out);
    k_finalize<<<1, 256>>>(out);
}

// round 5
// speedup vs baseline: 1.3973x; 1.3973x over previous
#include <cuda_runtime.h>
#include <math.h>

// Problem constants
#define BB   16
#define CC   1024
#define HH   32
#define WW   32
#define NE   256
#define NPIX (BB*HH*WW)          // 16384
#define OUT_ELEMS (BB*CC*HH*WW)  // 16777216
#define LOSS_OFF  OUT_ELEMS
#define PERP_OFF  (OUT_ELEMS+1)
#define IDX_OFF   (OUT_ELEMS+2)

// Scratch (no cudaMalloc allowed)
__device__ float g_code_out[CC*NE];   // TRANSPOSED: [o][j] = conv_w[o].emb[j] + b[o]
__device__ float g_ee2[NE];           // |e_j|^2
__device__ int   g_idx[NPIX];
__device__ int   g_counts[NE];
__device__ float g_loss_sum;

// ---------------------------------------------------------------------------
// Kernel 0: |e_j|^2 per code + reset accumulators
// ---------------------------------------------------------------------------
__global__ void k_ee2_reset(const float* __restrict__ emb) {
    int j = blockIdx.x;          // 256 blocks
    int t = threadIdx.x;         // 256 threads
    float s = 0.f;
    for (int c = t; c < CC; c += 256) {
        float v = emb[j*CC + c];
        s += v*v;
    }
    __shared__ float red[256];
    red[t] = s; __syncthreads();
    for (int st = 128; st > 0; st >>= 1) {
        if (t < st) red[t] += red[t+st];
        __syncthreads();
    }
    if (t == 0) {
        g_ee2[j] = red[0];
        g_counts[j] = 0;
        if (j == 0) g_loss_sum = 0.f;
    }
}

// ---------------------------------------------------------------------------
// Kernel 1: code_out[o][j] = sum_c emb[j][c]*conv_w[o][c] + conv_b[o]
// (transposed store so scatter gathers stay within one 1KB row per o)
// ---------------------------------------------------------------------------
__global__ void __launch_bounds__(256) k_codeout(
    const float* __restrict__ emb, const float* __restrict__ w,
    const float* __restrict__ bias)
{
    __shared__ float es[16][64];
    __shared__ float ws[16][64];
    int t  = threadIdx.x;
    int o0 = blockIdx.x * 64;    // 16 tiles over O=1024
    int j0 = blockIdx.y * 64;    // 4  tiles over J=256
    int rl  = t & 63, grp = t >> 6;   // load mapping
    int tol = t & 15, tjl = t >> 4;   // compute mapping (16x16 threads)
    float acc[4][4] = {};

    for (int k0 = 0; k0 < CC; k0 += 16) {
        float4 fe = *(const float4*)&emb[(size_t)(j0+rl)*CC + k0 + grp*4];
        float4 fw = *(const float4*)&w  [(size_t)(o0+rl)*CC + k0 + grp*4];
        es[grp*4+0][rl]=fe.x; es[grp*4+1][rl]=fe.y; es[grp*4+2][rl]=fe.z; es[grp*4+3][rl]=fe.w;
        ws[grp*4+0][rl]=fw.x; ws[grp*4+1][rl]=fw.y; ws[grp*4+2][rl]=fw.z; ws[grp*4+3][rl]=fw.w;
        __syncthreads();
        #pragma unroll
        for (int kk = 0; kk < 16; kk++) {
            float er[4], wr[4];
            #pragma unroll
            for (int i = 0; i < 4; i++) { er[i] = es[kk][tjl*4+i]; wr[i] = ws[kk][tol*4+i]; }
            #pragma unroll
            for (int jy = 0; jy < 4; jy++)
                #pragma unroll
                for (int ox = 0; ox < 4; ox++)
                    acc[jy][ox] = fmaf(er[jy], wr[ox], acc[jy][ox]);
        }
        __syncthreads();
    }
    #pragma unroll
    for (int jy = 0; jy < 4; jy++)
        #pragma unroll
        for (int ox = 0; ox < 4; ox++) {
            int j = j0 + tjl*4 + jy;
            int o = o0 + tol*4 + ox;
            g_code_out[(size_t)o*NE + j] = acc[jy][ox] + bias[o];  // transposed
        }
}

// ---------------------------------------------------------------------------
// Kernel 2: per-pixel argmin_j (|e_j|^2 - 2 z.e_j), fused loss.
// 512 blocks x 128 threads. Block = 32 pixels x 256 codes.
// Thread: 8 pixels x 8 codes. Inner loop: 2 LDS.128(z,broadcast) +
// 8 scalar LDS(e, conflict-free) per 64 FFMA.
// loss partial = sum(min_d) + sum(z^2)  since (e-z)^2 = (|e|^2-2z.e) + z^2
// ---------------------------------------------------------------------------
__global__ void __launch_bounds__(128, 4) k_argmin(
    const float* __restrict__ z, const float* __restrict__ emb,
    float* __restrict__ out)
{
    int bh = blockIdx.x;              // 512 blocks; pixels bh*32..+31
    int b = bh >> 5, h = bh & 31;
    __shared__ float z_s[16][32];
    __shared__ float e_s[16][256];
    __shared__ unsigned long long sKey[32];
    __shared__ float red[128];
    int t  = threadIdx.x;
    int tc = t & 31;                  // code lane -> codes tc+32g
    int pg = t >> 5;                  // pixel group (== warp id) -> pixels pg*8..+7

    if (t < 32) sKey[t] = ~0ull;

    float acc[8][8];
    #pragma unroll
    for (int i = 0; i < 8; i++)
        #pragma unroll
        for (int g = 0; g < 8; g++) acc[i][g] = 0.f;

    float zsq = 0.f;
    const float* zb = z + (size_t)b*(CC*HH*WW) + h*WW;  // + c*1024 + w

    for (int k0 = 0; k0 < CC; k0 += 16) {
        // z chunk: 16 k x 32 w (512 floats, 4/thread, coalesced); fold z^2 sum
        #pragma unroll
        for (int r = 0; r < 4; r++) {
            int i = t + 128*r;
            float v = zb[(size_t)(k0 + (i>>5))*(HH*WW) + (i&31)];
            z_s[i>>5][i&31] = v;
            zsq = fmaf(v, v, zsq);
        }
        // emb chunk: 256 codes x 16 k; thread loads codes t and t+128
        #pragma unroll
        for (int hh = 0; hh < 2; hh++) {
            int code = t + 128*hh;
            const float4* ep = (const float4*)&emb[(size_t)code*CC + k0];
            #pragma unroll
            for (int q = 0; q < 4; q++) {
                float4 f = ep[q];
                e_s[q*4+0][code]=f.x; e_s[q*4+1][code]=f.y;
                e_s[q*4+2][code]=f.z; e_s[q*4+3][code]=f.w;
            }
        }
        __syncthreads();
        #pragma unroll
        for (int kk = 0; kk < 16; kk++) {
            float4 za = *(const float4*)&z_s[kk][pg*8];      // broadcast in warp
            float4 zc = *(const float4*)&z_s[kk][pg*8+4];
            float zr[8] = {za.x, za.y, za.z, za.w, zc.x, zc.y, zc.z, zc.w};
            float er[8];
            #pragma unroll
            for (int g = 0; g < 8; g++) er[g] = e_s[kk][tc + 32*g];  // conflict-free
            #pragma unroll
            for (int i = 0; i < 8; i++)
                #pragma unroll
                for (int g = 0; g < 8; g++)
                    acc[i][g] = fmaf(zr[i], er[g], acc[i][g]);
        }
        __syncthreads();
    }

    float ee[8];
    #pragma unroll
    for (int g = 0; g < 8; g++) ee[g] = g_ee2[tc + 32*g];

    #pragma unroll
    for (int i = 0; i < 8; i++) {
        unsigned long long bk = ~0ull;
        #pragma unroll
        for (int g = 0; g < 8; g++) {
            int j = tc + 32*g;
            float s = ee[g] - 2.f*acc[i][g];
            unsigned u = __float_as_uint(s);
            u = (u & 0x80000000u) ? ~u : (u | 0x80000000u);   // order-preserving map
            unsigned long long key = ((unsigned long long)u << 32) | (unsigned)j;
            bk = (key < bk) ? key : bk;                        // ties -> lower j
        }
        atomicMin(&sKey[pg*8 + i], bk);
    }

    // block-reduce z^2
    red[t] = zsq; __syncthreads();
    for (int st = 64; st > 0; st >>= 1) {
        if (t < st) red[t] += red[t+st];
        __syncthreads();
    }

    if (t < 32) {
        unsigned long long k = sKey[t];
        int j = (int)(k & 0xFFFFFFFFu);
        unsigned u = (unsigned)(k >> 32);
        unsigned fb = (u & 0x80000000u) ? (u & 0x7FFFFFFFu) : ~u;  // undo map
        float dmin = __uint_as_float(fb);
        int n = bh*32 + t;
        g_idx[n] = j;
        atomicAdd(&g_counts[j], 1);
        out[IDX_OFF + n] = (float)j;
        // warp-reduce the 32 min distances
        #pragma unroll
        for (int o = 16; o > 0; o >>= 1)
            dmin += __shfl_down_sync(0xFFFFFFFFu, dmin, o);
        if (t == 0) atomicAdd(&g_loss_sum, dmin + red[0]);
    }
}

// ---------------------------------------------------------------------------
// Kernel 3: pure gather-scatter. out[b,o,h,w] = code_out[o][idx[b,h,w]].
// Block = (b, 32 o's). code_out rows staged in smem; float4 coalesced stores.
// ---------------------------------------------------------------------------
__global__ void __launch_bounds__(256) k_scatter(float* __restrict__ out)
{
    int bid = blockIdx.x;       // 512 = 16 b x 32 o-chunks
    int b  = bid >> 5;
    int oc = bid & 31;
    __shared__ int   idx_s[1024];
    __shared__ float ct[32*256];
    int t = threadIdx.x;
    #pragma unroll
    for (int r = 0; r < 4; r++)
        idx_s[t + 256*r] = g_idx[b*1024 + t + 256*r];
    const float4* src = (const float4*)(g_code_out + (size_t)oc*32*NE);
    float4* dst = (float4*)ct;
    #pragma unroll
    for (int r = 0; r < 8; r++)
        dst[t + 256*r] = src[t + 256*r];
    __syncthreads();

    int warp = t >> 5, lane = t & 31;
    float* ob = out + (size_t)b*(CC*HH*WW) + (size_t)oc*32*(HH*WW);
    #pragma unroll
    for (int q = 0; q < 4; q++) {
        int o = warp*4 + q;
        const float* crow = &ct[o*NE];
        #pragma unroll
        for (int p0 = 0; p0 < 1024; p0 += 128) {
            int4 j4 = *(const int4*)&idx_s[p0 + lane*4];
            float4 v;
            v.x = crow[j4.x]; v.y = crow[j4.y];
            v.z = crow[j4.z]; v.w = crow[j4.w];
            *(float4*)&ob[(size_t)o*(HH*WW) + p0 + lane*4] = v;
        }
    }
}

// ---------------------------------------------------------------------------
// Kernel 4: finalize loss + perplexity
// ---------------------------------------------------------------------------
__global__ void k_finalize(float* __restrict__ out) {
    int t = threadIdx.x;   // 256 threads, 1 block
    float em = (float)g_counts[t] / (float)NPIX;
    float term = em * logf(em + 1e-10f);
    __shared__ float red[256];
    red[t] = term; __syncthreads();
    for (int st = 128; st > 0; st >>= 1) {
        if (t < st) red[t] += red[t+st];
        __syncthreads();
    }
    if (t == 0) {
        out[LOSS_OFF] = 1.25f * g_loss_sum / (float)OUT_ELEMS;  // (1+BETA)*mse
        out[PERP_OFF] = expf(-red[0]);
    }
}

// ---------------------------------------------------------------------------
extern "C" void kernel_launch(void* const* d_in, const int* in_sizes, int n_in,
                              void* d_out, int out_size) {
    const float* z      = (const float*)d_in[0];
    const float* emb    = (const float*)d_in[1];
    const float* conv_w = (const float*)d_in[2];
    const float* conv_b = (const float*)d_in[3];
    float* out = (float*)d_out;

    k_ee2_reset<<<NE, 256>>>(emb);
    k_codeout<<<dim3(CC/64, NE/64), 256>>>(emb, conv_w, conv_b);
    k_argmin<<<BB*HH, 128>>>(z, emb, out);
    k_scatter<<<BB*HH, 256>>>(out);
    k_finalize<<<1, 256>>>(out);
}

// round 8
// speedup vs baseline: 2.3232x; 1.6627x over previous
#include <cuda_runtime.h>
#include <cuda_bf16.h>
#include <math.h>
#include <stdint.h>

// Problem constants
#define BB   16
#define CC   1024
#define HH   32
#define WW   32
#define NE   256
#define NPIX (BB*HH*WW)          // 16384
#define OUT_ELEMS (BB*CC*HH*WW)  // 16777216
#define LOSS_OFF  OUT_ELEMS
#define PERP_OFF  (OUT_ELEMS+1)
#define IDX_OFF   (OUT_ELEMS+2)

#define KCHUNK 32
#define NCHUNK (CC/KCHUNK)       // 32

// Scratch (no cudaMalloc allowed)
__device__ float g_code_out[CC*NE];   // TRANSPOSED: [o][j]
__device__ float g_ee2[NE];
__device__ int   g_idx[NPIX];
__device__ int   g_counts[NE];
__device__ float g_loss_sum;
// e splits (tf32 bit patterns in float), pre-permuted into m16n8k8 B-fragment
// order: [split(2)][chunk(32)][kt(4)][nt(32)][lane(32)][slot(2)]  = 2 MB
__device__ float g_es2[2*NCHUNK*4*32*32*2];

// ---------------------------------------------------------------------------
__device__ __forceinline__ uint32_t f2tf32(float x) {
    uint32_t r;
    asm("cvt.rna.tf32.f32 %0, %1;" : "=r"(r) : "f"(x));
    return r;
}
__device__ __forceinline__ void mma_tf32(float c[4],
    uint32_t a0, uint32_t a1, uint32_t a2, uint32_t a3,
    uint32_t b0, uint32_t b1)
{
    asm volatile(
        "mma.sync.aligned.m16n8k8.row.col.f32.tf32.tf32.f32 "
        "{%0,%1,%2,%3}, {%4,%5,%6,%7}, {%8,%9}, {%0,%1,%2,%3};"
        : "+f"(c[0]), "+f"(c[1]), "+f"(c[2]), "+f"(c[3])
        : "r"(a0), "r"(a1), "r"(a2), "r"(a3), "r"(b0), "r"(b1));
}

// ---------------------------------------------------------------------------
// Kernel 0: |e_j|^2 + reset accumulators
// ---------------------------------------------------------------------------
__global__ void k_ee2_reset(const float* __restrict__ emb) {
    int j = blockIdx.x, t = threadIdx.x;
    float s = 0.f;
    for (int c = t; c < CC; c += 256) { float v = emb[j*CC + c]; s += v*v; }
    __shared__ float red[256];
    red[t] = s; __syncthreads();
    for (int st = 128; st > 0; st >>= 1) { if (t < st) red[t] += red[t+st]; __syncthreads(); }
    if (t == 0) { g_ee2[j] = red[0]; g_counts[j] = 0; if (j == 0) g_loss_sum = 0.f; }
}

// ---------------------------------------------------------------------------
// Kernel 0b: 2-way tf32 split of emb, pre-permuted into B-fragment layout.
// m16n8k8 B frag: for (k row kk, n col): lane = (n&7)*4 + (kk&3), slot = kk>>2
// ---------------------------------------------------------------------------
__global__ void k_esplit(const float* __restrict__ emb) {
    int j = blockIdx.x, t = threadIdx.x;     // 256 blocks x 256 threads
    #pragma unroll
    for (int i = 0; i < 4; i++) {
        int k = t*4 + i;
        float x = emb[(size_t)j*CC + k];
        uint32_t hi = f2tf32(x);
        uint32_t lo = f2tf32(x - __uint_as_float(hi));
        int chunk = k >> 5, kk5 = k & 31;
        int kt = kk5 >> 3, kk = kk5 & 7;
        int nt = j >> 3;
        int lane = (j & 7)*4 + (kk & 3);
        int slot = kk >> 2;
        size_t off = (((size_t)kt*32 + nt)*32 + lane)*2 + slot;
        ((uint32_t*)g_es2)[((size_t)(0*NCHUNK + chunk))*8192 + off] = hi;
        ((uint32_t*)g_es2)[((size_t)(1*NCHUNK + chunk))*8192 + off] = lo;
    }
}

// ---------------------------------------------------------------------------
// Kernel 1: code_out[o][j] = emb[j].conv_w[o] + b[o]   (fp32, transposed out)
// ---------------------------------------------------------------------------
__global__ void __launch_bounds__(256) k_codeout(
    const float* __restrict__ emb, const float* __restrict__ w,
    const float* __restrict__ bias)
{
    __shared__ float es[16][64];
    __shared__ float ws[16][64];
    int t  = threadIdx.x;
    int o0 = blockIdx.x * 64, j0 = blockIdx.y * 64;
    int rl = t & 63, grp = t >> 6;
    int tol = t & 15, tjl = t >> 4;
    float acc[4][4] = {};
    for (int k0 = 0; k0 < CC; k0 += 16) {
        float4 fe = *(const float4*)&emb[(size_t)(j0+rl)*CC + k0 + grp*4];
        float4 fw = *(const float4*)&w  [(size_t)(o0+rl)*CC + k0 + grp*4];
        es[grp*4+0][rl]=fe.x; es[grp*4+1][rl]=fe.y; es[grp*4+2][rl]=fe.z; es[grp*4+3][rl]=fe.w;
        ws[grp*4+0][rl]=fw.x; ws[grp*4+1][rl]=fw.y; ws[grp*4+2][rl]=fw.z; ws[grp*4+3][rl]=fw.w;
        __syncthreads();
        #pragma unroll
        for (int kk = 0; kk < 16; kk++) {
            float er[4], wr[4];
            #pragma unroll
            for (int i = 0; i < 4; i++) { er[i] = es[kk][tjl*4+i]; wr[i] = ws[kk][tol*4+i]; }
            #pragma unroll
            for (int jy = 0; jy < 4; jy++)
                #pragma unroll
                for (int ox = 0; ox < 4; ox++)
                    acc[jy][ox] = fmaf(er[jy], wr[ox], acc[jy][ox]);
        }
        __syncthreads();
    }
    #pragma unroll
    for (int jy = 0; jy < 4; jy++)
        #pragma unroll
        for (int ox = 0; ox < 4; ox++)
            g_code_out[(size_t)(o0+tol*4+ox)*NE + (j0+tjl*4+jy)] = acc[jy][ox] + bias[o0+tol*4+ox];
}

// ---------------------------------------------------------------------------
// Kernel 2: 3xTF32 warp-MMA argmin. 128 CTAs x 256 thr (8 warps, 2x4 grid).
// CTA: M=128 pixels x N=256 codes, K=1024 in 32 chunks of 32.
// A (z) split to (hi,lo) tf32 on the fly, stored in A-fragment order.
// B (e) splits pre-permuted in g_es2. acc += zh*eh + zh*el + zl*eh (fp32 acc).
// score_j = |e_j|^2 - 2 z.e_j ; fused loss = sum(min) + sum(z^2).
// ---------------------------------------------------------------------------
// A_s: [plane(2)][kt(4)][mt(8)][lane(32)][slot(4)] floats = 8192 fl = 32 KB
// B_s: [split(2)][kt(4)][nt(32)][lane(32)][slot(2)] floats = 16384 fl = 64 KB
#define ASZ 8192
#define DYN_SMEM ((ASZ + 16384) * 4)

__global__ void __launch_bounds__(256, 1) k_argmin_tc(
    const float* __restrict__ z, float* __restrict__ out)
{
    extern __shared__ float smem[];
    float* As = smem;              // 8192 floats
    float* Bs = smem + ASZ;        // 16384 floats
    __shared__ unsigned long long sKey[128];
    __shared__ float redf[256];
    __shared__ float ee2_s[NE];

    int t = threadIdx.x, lane = t & 31, w = t >> 5;
    int wm = w >> 2, wn = w & 3;         // warp grid 2 (M) x 4 (N)
    int g = lane >> 2, tig = lane & 3;
    int cta = blockIdx.x;                // 128 CTAs
    int bb = cta >> 3;                   // pixels cta*128: batch
    int p0 = (cta & 7) * 128;

    if (t < 128) sKey[t] = ~0ull;
    ee2_s[t] = g_ee2[t];

    float acc[4][8][4];
    #pragma unroll
    for (int m = 0; m < 4; m++)
        #pragma unroll
        for (int n = 0; n < 8; n++)
            #pragma unroll
            for (int q = 0; q < 4; q++) acc[m][n][q] = 0.f;

    float zsq = 0.f;
    const float* zb = z + (size_t)bb*(CC*1024) + p0;

    for (int ch = 0; ch < NCHUNK; ch++) {
        __syncthreads();   // prev compute done (and first-iter init) before overwrite

        // --- stage A: warp w owns tiles w*4..w*4+3 of the 32 (kt,mt) tiles ---
        #pragma unroll
        for (int i = 0; i < 4; i++) {
            int tile = w*4 + i;
            int kt = tile >> 3, mt = tile & 7;
            int c = ch*KCHUNK + kt*8 + tig;
            int p = mt*16 + g;
            const float* zp = zb + (size_t)c*1024 + p;
            float v00 = zp[0];
            float v10 = zp[8];
            float v01 = zp[4*1024];
            float v11 = zp[4*1024 + 8];
            zsq = fmaf(v00, v00, zsq); zsq = fmaf(v10, v10, zsq);
            zsq = fmaf(v01, v01, zsq); zsq = fmaf(v11, v11, zsq);
            uint32_t h00 = f2tf32(v00), h10 = f2tf32(v10);
            uint32_t h01 = f2tf32(v01), h11 = f2tf32(v11);
            uint32_t l00 = f2tf32(v00 - __uint_as_float(h00));
            uint32_t l10 = f2tf32(v10 - __uint_as_float(h10));
            uint32_t l01 = f2tf32(v01 - __uint_as_float(h01));
            uint32_t l11 = f2tf32(v11 - __uint_as_float(h11));
            uint4 hv = make_uint4(h00, h10, h01, h11);
            uint4 lv = make_uint4(l00, l10, l01, l11);
            int base = ((kt*8 + mt)*32 + lane)*4;
            *(uint4*)&As[base]       = hv;
            *(uint4*)&As[4096 + base] = lv;
        }
        // --- stage B: straight copies of pre-permuted chunk planes ---
        {
            const uint4* s0 = (const uint4*)(g_es2 + (size_t)ch*8192);
            const uint4* s1 = (const uint4*)(g_es2 + (size_t)(NCHUNK + ch)*8192);
            uint4* d0 = (uint4*)Bs;
            uint4* d1 = (uint4*)(Bs + 8192);
            #pragma unroll
            for (int r = 0; r < 8; r++) {
                d0[t + 256*r] = s0[t + 256*r];
                d1[t + 256*r] = s1[t + 256*r];
            }
        }
        __syncthreads();

        // --- compute: 4 ktiles x (4 mt x 8 nt) x 3 MMA ---
        #pragma unroll
        for (int kt = 0; kt < 4; kt++) {
            uint4 ah[4], al[4];
            #pragma unroll
            for (int m = 0; m < 4; m++) {
                int base = ((kt*8 + wm*4 + m)*32 + lane)*4;
                ah[m] = *(const uint4*)&As[base];
                al[m] = *(const uint4*)&As[4096 + base];
            }
            #pragma unroll
            for (int n = 0; n < 8; n++) {
                int bbase = ((kt*32 + wn*8 + n)*32 + lane)*2;
                uint2 bh = *(const uint2*)&Bs[bbase];
                uint2 bl = *(const uint2*)&Bs[8192 + bbase];
                #pragma unroll
                for (int m = 0; m < 4; m++) {
                    mma_tf32(acc[m][n], ah[m].x, ah[m].y, ah[m].z, ah[m].w, bh.x, bh.y);
                    mma_tf32(acc[m][n], ah[m].x, ah[m].y, ah[m].z, ah[m].w, bl.x, bl.y);
                    mma_tf32(acc[m][n], al[m].x, al[m].y, al[m].z, al[m].w, bh.x, bh.y);
                }
            }
        }
    }

    // --- epilogue: per-thread min over its 16 codes for each of 8 pixels ---
    #pragma unroll
    for (int m = 0; m < 4; m++) {
        unsigned long long b0 = ~0ull, b1 = ~0ull;
        #pragma unroll
        for (int n = 0; n < 8; n++) {
            int j0 = wn*64 + n*8 + tig*2;
            #pragma unroll
            for (int q = 0; q < 2; q++) {
                float s_lo = ee2_s[j0+q] - 2.f*acc[m][n][q];     // pixel row g
                float s_hi = ee2_s[j0+q] - 2.f*acc[m][n][q+2];   // pixel row g+8
                unsigned u0 = __float_as_uint(s_lo);
                u0 = (u0 & 0x80000000u) ? ~u0 : (u0 | 0x80000000u);
                unsigned long long k0 = ((unsigned long long)u0 << 32) | (unsigned)(j0+q);
                b0 = (k0 < b0) ? k0 : b0;
                unsigned u1 = __float_as_uint(s_hi);
                u1 = (u1 & 0x80000000u) ? ~u1 : (u1 | 0x80000000u);
                unsigned long long k1 = ((unsigned long long)u1 << 32) | (unsigned)(j0+q);
                b1 = (k1 < b1) ? k1 : b1;
            }
        }
        int prow = wm*64 + m*16 + g;
        atomicMin(&sKey[prow], b0);
        atomicMin(&sKey[prow + 8], b1);
    }
    __syncthreads();

    float dmin = 0.f;
    if (t < 128) {
        unsigned long long k = sKey[t];
        int j = (int)(k & 0xFFFFFFFFu);
        unsigned u = (unsigned)(k >> 32);
        unsigned fb = (u & 0x80000000u) ? (u & 0x7FFFFFFFu) : ~u;
        dmin = __uint_as_float(fb);
        int n = cta*128 + t;
        g_idx[n] = j;
        atomicAdd(&g_counts[j], 1);
        out[IDX_OFF + n] = (float)j;
    }

    redf[t] = zsq + dmin;
    __syncthreads();
    for (int st = 128; st > 0; st >>= 1) { if (t < st) redf[t] += redf[t+st]; __syncthreads(); }
    if (t == 0) atomicAdd(&g_loss_sum, redf[0]);
}

// ---------------------------------------------------------------------------
// Kernel 3: gather-scatter. out[b,o,h,w] = code_out[o][idx[b,h,w]].
// ---------------------------------------------------------------------------
__global__ void __launch_bounds__(256) k_scatter(float* __restrict__ out)
{
    int bid = blockIdx.x;
    int b  = bid >> 5, oc = bid & 31;
    __shared__ int   idx_s[1024];
    __shared__ float ct[32*256];
    int t = threadIdx.x;
    #pragma unroll
    for (int r = 0; r < 4; r++) idx_s[t + 256*r] = g_idx[b*1024 + t + 256*r];
    const float4* src = (const float4*)(g_code_out + (size_t)oc*32*NE);
    float4* dst = (float4*)ct;
    #pragma unroll
    for (int r = 0; r < 8; r++) dst[t + 256*r] = src[t + 256*r];
    __syncthreads();
    int warp = t >> 5, lane = t & 31;
    float* ob = out + (size_t)b*(CC*HH*WW) + (size_t)oc*32*(HH*WW);
    #pragma unroll
    for (int q = 0; q < 4; q++) {
        int o = warp*4 + q;
        const float* crow = &ct[o*NE];
        #pragma unroll
        for (int p0 = 0; p0 < 1024; p0 += 128) {
            int4 j4 = *(const int4*)&idx_s[p0 + lane*4];
            float4 v;
            v.x = crow[j4.x]; v.y = crow[j4.y]; v.z = crow[j4.z]; v.w = crow[j4.w];
            *(float4*)&ob[(size_t)o*(HH*WW) + p0 + lane*4] = v;
        }
    }
}

// ---------------------------------------------------------------------------
// Kernel 4: finalize loss + perplexity
// ---------------------------------------------------------------------------
__global__ void k_finalize(float* __restrict__ out) {
    int t = threadIdx.x;
    float em = (float)g_counts[t] / (float)NPIX;
    float term = em * logf(em + 1e-10f);
    __shared__ float red[256];
    red[t] = term; __syncthreads();
    for (int st = 128; st > 0; st >>= 1) { if (t < st) red[t] += red[t+st]; __syncthreads(); }
    if (t == 0) {
        out[LOSS_OFF] = 1.25f * g_loss_sum / (float)OUT_ELEMS;
        out[PERP_OFF] = expf(-red[0]);
    }
}

// ---------------------------------------------------------------------------
extern "C" void kernel_launch(void* const* d_in, const int* in_sizes, int n_in,
                              void* d_out, int out_size) {
    const float* z      = (const float*)d_in[0];
    const float* emb    = (const float*)d_in[1];
    const float* conv_w = (const float*)d_in[2];
    const float* conv_b = (const float*)d_in[3];
    float* out = (float*)d_out;

    cudaFuncSetAttribute(k_argmin_tc, cudaFuncAttributeMaxDynamicSharedMemorySize, DYN_SMEM);

    k_ee2_reset<<<NE, 256>>>(emb);
    k_esplit<<<NE, 256>>>(emb);
    k_codeout<<<dim3(CC/64, NE/64), 256>>>(emb, conv_w, conv_b);
    k_argmin_tc<<<NPIX/128, 256, DYN_SMEM>>>(z, out);
    k_scatter<<<BB*HH, 256>>>(out);
    k_finalize<<<1, 256>>>(out);
}

// round 10
// speedup vs baseline: 2.4649x; 1.0610x over previous
#include <cuda_runtime.h>
#include <cuda_bf16.h>
#include <math.h>
#include <stdint.h>

// Problem constants
#define BB   16
#define CC   1024
#define HH   32
#define WW   32
#define NE   256
#define NPIX (BB*HH*WW)          // 16384
#define OUT_ELEMS (BB*CC*HH*WW)  // 16777216
#define LOSS_OFF  OUT_ELEMS
#define PERP_OFF  (OUT_ELEMS+1)
#define IDX_OFF   (OUT_ELEMS+2)

#define KCHUNK 16
#define NCHUNK (CC/KCHUNK)       // 64

// Scratch (no cudaMalloc allowed)
__device__ float g_code_out[CC*NE];   // TRANSPOSED: [o][j]
__device__ float g_ee2[NE];
__device__ int   g_idx[NPIX];
__device__ int   g_counts[NE];
__device__ float g_loss_sum;
// e splits (tf32 bit patterns), pre-permuted into m16n8k8 B-fragment order:
// [split(2)][chunk(64)][kt(2)][nt(32)][lane(32)][slot(2)]  = 2 MB
#define CHW 4096   // words per (split,chunk) plane
__device__ __align__(16) float g_es2[2*NCHUNK*CHW];

// ---------------------------------------------------------------------------
__device__ __forceinline__ uint32_t f2tf32(float x) {
    uint32_t r;
    asm("cvt.rna.tf32.f32 %0, %1;" : "=r"(r) : "f"(x));
    return r;
}
__device__ __forceinline__ void mma_tf32(float c[4],
    uint32_t a0, uint32_t a1, uint32_t a2, uint32_t a3,
    uint32_t b0, uint32_t b1)
{
    asm volatile(
        "mma.sync.aligned.m16n8k8.row.col.f32.tf32.tf32.f32 "
        "{%0,%1,%2,%3}, {%4,%5,%6,%7}, {%8,%9}, {%0,%1,%2,%3};"
        : "+f"(c[0]), "+f"(c[1]), "+f"(c[2]), "+f"(c[3])
        : "r"(a0), "r"(a1), "r"(a2), "r"(a3), "r"(b0), "r"(b1));
}
__device__ __forceinline__ uint32_t smem_u32(const void* p) {
    uint32_t a;
    asm("{ .reg .u64 t; cvta.to.shared.u64 t, %1; cvt.u32.u64 %0, t; }" : "=r"(a) : "l"(p));
    return a;
}
__device__ __forceinline__ void cp_async16(uint32_t saddr, const void* g) {
    asm volatile("cp.async.cg.shared.global [%0], [%1], 16;" :: "r"(saddr), "l"(g));
}
#define CP_COMMIT() asm volatile("cp.async.commit_group;")
#define CP_WAIT0()  asm volatile("cp.async.wait_group 0;" ::: "memory")

// ---------------------------------------------------------------------------
// Kernel 0: |e_j|^2 + reset accumulators
// ---------------------------------------------------------------------------
__global__ void k_ee2_reset(const float* __restrict__ emb) {
    int j = blockIdx.x, t = threadIdx.x;
    float s = 0.f;
    for (int c = t; c < CC; c += 256) { float v = emb[j*CC + c]; s += v*v; }
    __shared__ float red[256];
    red[t] = s; __syncthreads();
    for (int st = 128; st > 0; st >>= 1) { if (t < st) red[t] += red[t+st]; __syncthreads(); }
    if (t == 0) { g_ee2[j] = red[0]; g_counts[j] = 0; if (j == 0) g_loss_sum = 0.f; }
}

// ---------------------------------------------------------------------------
// Kernel 0b: 2-way tf32 split of emb, B-fragment permuted, OUTPUT-coalesced.
// Inverse map: slot=o&1, lane=(o>>1)&31, nt=(o>>6)&31, kt=(o>>11)&1
//              j = nt*8 + (lane>>2), k = ch*16 + kt*8 + (lane&3) + 4*slot
// ---------------------------------------------------------------------------
__global__ void k_esplit(const float* __restrict__ emb) {
    int ch = blockIdx.x, t = threadIdx.x;     // 64 blocks x 256 threads
    uint32_t* hi_out = (uint32_t*)g_es2 + (size_t)ch*CHW;
    uint32_t* lo_out = (uint32_t*)g_es2 + (size_t)(NCHUNK + ch)*CHW;
    #pragma unroll
    for (int r = 0; r < 16; r++) {
        int o = t + 256*r;
        int slot = o & 1, lane = (o >> 1) & 31, nt = (o >> 6) & 31, kt = (o >> 11) & 1;
        int j = nt*8 + (lane >> 2);
        int k = ch*16 + kt*8 + (lane & 3) + 4*slot;
        float x = emb[(size_t)j*CC + k];
        uint32_t hi = f2tf32(x);
        uint32_t lo = f2tf32(x - __uint_as_float(hi));
        hi_out[o] = hi;
        lo_out[o] = lo;
    }
}

// ---------------------------------------------------------------------------
// Kernel 1: code_out[o][j] = emb[j].conv_w[o] + b[o]   (fp32, transposed out)
// ---------------------------------------------------------------------------
__global__ void __launch_bounds__(256) k_codeout(
    const float* __restrict__ emb, const float* __restrict__ w,
    const float* __restrict__ bias)
{
    __shared__ float es[16][64];
    __shared__ float ws[16][64];
    int t  = threadIdx.x;
    int o0 = blockIdx.x * 64, j0 = blockIdx.y * 64;
    int rl = t & 63, grp = t >> 6;
    int tol = t & 15, tjl = t >> 4;
    float acc[4][4] = {};
    for (int k0 = 0; k0 < CC; k0 += 16) {
        float4 fe = *(const float4*)&emb[(size_t)(j0+rl)*CC + k0 + grp*4];
        float4 fw = *(const float4*)&w  [(size_t)(o0+rl)*CC + k0 + grp*4];
        es[grp*4+0][rl]=fe.x; es[grp*4+1][rl]=fe.y; es[grp*4+2][rl]=fe.z; es[grp*4+3][rl]=fe.w;
        ws[grp*4+0][rl]=fw.x; ws[grp*4+1][rl]=fw.y; ws[grp*4+2][rl]=fw.z; ws[grp*4+3][rl]=fw.w;
        __syncthreads();
        #pragma unroll
        for (int kk = 0; kk < 16; kk++) {
            float er[4], wr[4];
            #pragma unroll
            for (int i = 0; i < 4; i++) { er[i] = es[kk][tjl*4+i]; wr[i] = ws[kk][tol*4+i]; }
            #pragma unroll
            for (int jy = 0; jy < 4; jy++)
                #pragma unroll
                for (int ox = 0; ox < 4; ox++)
                    acc[jy][ox] = fmaf(er[jy], wr[ox], acc[jy][ox]);
        }
        __syncthreads();
    }
    #pragma unroll
    for (int jy = 0; jy < 4; jy++)
        #pragma unroll
        for (int ox = 0; ox < 4; ox++)
            g_code_out[(size_t)(o0+tol*4+ox)*NE + (j0+tjl*4+jy)] = acc[jy][ox] + bias[o0+tol*4+ox];
}

// ---------------------------------------------------------------------------
// Kernel 2: 3xTF32 warp-MMA argmin, cp.async double-buffered pipeline.
// 128 CTAs x 256 thr (8 warps 2x4). CTA tile M=128 x N=256, K=1024/16-chunks.
// ---------------------------------------------------------------------------
// Per buffer: A = 2 planes x 2048 fl (16KB), B = 2 splits x 4096 fl (32KB)
#define A_BUF 4096
#define B_BUF 8192
#define DYN_SMEM ((2*A_BUF + 2*B_BUF) * 4)   // 96 KB

__global__ void __launch_bounds__(256, 1) k_argmin_tc(
    const float* __restrict__ z, float* __restrict__ out)
{
    extern __shared__ float smem[];
    float* As = smem;                  // 2 x A_BUF
    float* Bs = smem + 2*A_BUF;        // 2 x B_BUF
    __shared__ unsigned long long sKey[128];
    __shared__ float redf[256];
    __shared__ float ee2_s[NE];

    int t = threadIdx.x, lane = t & 31, w = t >> 5;
    int wm = w >> 2, wn = w & 3;         // warp grid 2 (M) x 4 (N)
    int g = lane >> 2, tig = lane & 3;
    int cta = blockIdx.x;                // 128 CTAs
    int bb = cta >> 3;
    int p0 = (cta & 7) * 128;

    if (t < 128) sKey[t] = ~0ull;
    ee2_s[t] = g_ee2[t];

    uint32_t bs_addr = smem_u32(Bs);

    float acc[4][8][4];
    #pragma unroll
    for (int m = 0; m < 4; m++)
        #pragma unroll
        for (int n = 0; n < 8; n++)
            #pragma unroll
            for (int q = 0; q < 4; q++) acc[m][n][q] = 0.f;

    float zsq = 0.f;
    const float* zb = z + (size_t)bb*(CC*1024) + p0;

    // A tiles: 16 (kt2 x mt8) per chunk; warp w owns tiles w*2, w*2+1.
    int tile0 = w*2;
    int kt_a[2], mt_a[2];
    kt_a[0] = tile0 >> 3;      mt_a[0] = tile0 & 7;
    kt_a[1] = (tile0+1) >> 3;  mt_a[1] = (tile0+1) & 7;

    float zr[8];   // prefetch registers (2 tiles x 4 vals)

    auto ld_a = [&](int ch) {
        #pragma unroll
        for (int i = 0; i < 2; i++) {
            const float* zp = zb + (size_t)(ch*16 + kt_a[i]*8 + tig)*1024 + mt_a[i]*16 + g;
            zr[i*4+0] = zp[0];
            zr[i*4+1] = zp[8];
            zr[i*4+2] = zp[4*1024];
            zr[i*4+3] = zp[4*1024 + 8];
        }
    };
    auto cvt_a = [&](int buf) {
        #pragma unroll
        for (int i = 0; i < 2; i++) {
            float v0 = zr[i*4+0], v1 = zr[i*4+1], v2 = zr[i*4+2], v3 = zr[i*4+3];
            zsq = fmaf(v0,v0,zsq); zsq = fmaf(v1,v1,zsq);
            zsq = fmaf(v2,v2,zsq); zsq = fmaf(v3,v3,zsq);
            uint32_t h0=f2tf32(v0), h1=f2tf32(v1), h2=f2tf32(v2), h3=f2tf32(v3);
            uint32_t l0=f2tf32(v0-__uint_as_float(h0));
            uint32_t l1=f2tf32(v1-__uint_as_float(h1));
            uint32_t l2=f2tf32(v2-__uint_as_float(h2));
            uint32_t l3=f2tf32(v3-__uint_as_float(h3));
            int base = buf*A_BUF + ((kt_a[i]*8 + mt_a[i])*32 + lane)*4;
            *(uint4*)&As[base]        = make_uint4(h0,h1,h2,h3);
            *(uint4*)&As[base + 2048] = make_uint4(l0,l1,l2,l3);
        }
    };
    auto issue_b = [&](int ch, int buf) {
        const float* s0 = g_es2 + (size_t)ch*CHW;
        const float* s1 = g_es2 + (size_t)(NCHUNK + ch)*CHW;
        uint32_t d0 = bs_addr + (buf*B_BUF)*4;
        uint32_t d1 = d0 + 4096*4;
        #pragma unroll
        for (int q = 0; q < 4; q++) {
            int idx = t + 256*q;
            cp_async16(d0 + idx*16, (const void*)(s0 + idx*4));
            cp_async16(d1 + idx*16, (const void*)(s1 + idx*4));
        }
    };
    auto compute = [&](int buf) {
        #pragma unroll
        for (int kt = 0; kt < 2; kt++) {
            uint4 ah[4], al[4];
            #pragma unroll
            for (int m = 0; m < 4; m++) {
                int base = buf*A_BUF + ((kt*8 + wm*4 + m)*32 + lane)*4;
                ah[m] = *(const uint4*)&As[base];
                al[m] = *(const uint4*)&As[base + 2048];
            }
            #pragma unroll
            for (int n = 0; n < 8; n++) {
                int bbase = buf*B_BUF + ((kt*32 + wn*8 + n)*32 + lane)*2;
                uint2 bh = *(const uint2*)&Bs[bbase];
                uint2 bl = *(const uint2*)&Bs[bbase + 4096];
                #pragma unroll
                for (int m = 0; m < 4; m++) {
                    mma_tf32(acc[m][n], ah[m].x, ah[m].y, ah[m].z, ah[m].w, bh.x, bh.y);
                    mma_tf32(acc[m][n], ah[m].x, ah[m].y, ah[m].z, ah[m].w, bl.x, bl.y);
                    mma_tf32(acc[m][n], al[m].x, al[m].y, al[m].z, al[m].w, bh.x, bh.y);
                }
            }
        }
    };

    // --- prologue: stage chunk 0 into buffer 0 ---
    issue_b(0, 0);
    ld_a(0);
    cvt_a(0);
    CP_COMMIT();
    CP_WAIT0();
    __syncthreads();

    // --- main pipeline ---
    for (int ch = 0; ch < NCHUNK; ch++) {
        int buf = ch & 1, nbuf = buf ^ 1;
        if (ch + 1 < NCHUNK) {
            issue_b(ch + 1, nbuf);
            CP_COMMIT();
            ld_a(ch + 1);
        }
        compute(buf);
        if (ch + 1 < NCHUNK) {
            cvt_a(nbuf);
            CP_WAIT0();
        }
        __syncthreads();
    }

    // --- epilogue: per-thread min over its 16 codes for each of 8 pixels ---
    #pragma unroll
    for (int m = 0; m < 4; m++) {
        unsigned long long b0 = ~0ull, b1 = ~0ull;
        #pragma unroll
        for (int n = 0; n < 8; n++) {
            int j0 = wn*64 + n*8 + tig*2;
            #pragma unroll
            for (int q = 0; q < 2; q++) {
                float s_lo = ee2_s[j0+q] - 2.f*acc[m][n][q];
                float s_hi = ee2_s[j0+q] - 2.f*acc[m][n][q+2];
                unsigned u0 = __float_as_uint(s_lo);
                u0 = (u0 & 0x80000000u) ? ~u0 : (u0 | 0x80000000u);
                unsigned long long k0 = ((unsigned long long)u0 << 32) | (unsigned)(j0+q);
                b0 = (k0 < b0) ? k0 : b0;
                unsigned u1 = __float_as_uint(s_hi);
                u1 = (u1 & 0x80000000u) ? ~u1 : (u1 | 0x80000000u);
                unsigned long long k1 = ((unsigned long long)u1 << 32) | (unsigned)(j0+q);
                b1 = (k1 < b1) ? k1 : b1;
            }
        }
        int prow = wm*64 + m*16 + g;
        atomicMin(&sKey[prow], b0);
        atomicMin(&sKey[prow + 8], b1);
    }
    __syncthreads();

    float dmin = 0.f;
    if (t < 128) {
        unsigned long long k = sKey[t];
        int j = (int)(k & 0xFFFFFFFFu);
        unsigned u = (unsigned)(k >> 32);
        unsigned fb = (u & 0x80000000u) ? (u & 0x7FFFFFFFu) : ~u;
        dmin = __uint_as_float(fb);
        int n = cta*128 + t;
        g_idx[n] = j;
        atomicAdd(&g_counts[j], 1);
        out[IDX_OFF + n] = (float)j;
    }

    redf[t] = zsq + dmin;
    __syncthreads();
    for (int st = 128; st > 0; st >>= 1) { if (t < st) redf[t] += redf[t+st]; __syncthreads(); }
    if (t == 0) atomicAdd(&g_loss_sum, redf[0]);
}

// ---------------------------------------------------------------------------
// Kernel 3: gather-scatter. out[b,o,h,w] = code_out[o][idx[b,h,w]].
// ---------------------------------------------------------------------------
__global__ void __launch_bounds__(256) k_scatter(float* __restrict__ out)
{
    int bid = blockIdx.x;
    int b  = bid >> 5, oc = bid & 31;
    __shared__ int   idx_s[1024];
    __shared__ float ct[32*256];
    int t = threadIdx.x;
    #pragma unroll
    for (int r = 0; r < 4; r++) idx_s[t + 256*r] = g_idx[b*1024 + t + 256*r];
    const float4* src = (const float4*)(g_code_out + (size_t)oc*32*NE);
    float4* dst = (float4*)ct;
    #pragma unroll
    for (int r = 0; r < 8; r++) dst[t + 256*r] = src[t + 256*r];
    __syncthreads();
    int warp = t >> 5, lane = t & 31;
    float* ob = out + (size_t)b*(CC*HH*WW) + (size_t)oc*32*(HH*WW);
    #pragma unroll
    for (int q = 0; q < 4; q++) {
        int o = warp*4 + q;
        const float* crow = &ct[o*NE];
        #pragma unroll
        for (int p0 = 0; p0 < 1024; p0 += 128) {
            int4 j4 = *(const int4*)&idx_s[p0 + lane*4];
            float4 v;
            v.x = crow[j4.x]; v.y = crow[j4.y]; v.z = crow[j4.z]; v.w = crow[j4.w];
            *(float4*)&ob[(size_t)o*(HH*WW) + p0 + lane*4] = v;
        }
    }
}

// ---------------------------------------------------------------------------
// Kernel 4: finalize loss + perplexity
// ---------------------------------------------------------------------------
__global__ void k_finalize(float* __restrict__ out) {
    int t = threadIdx.x;
    float em = (float)g_counts[t] / (float)NPIX;
    float term = em * logf(em + 1e-10f);
    __shared__ float red[256];
    red[t] = term; __syncthreads();
    for (int st = 128; st > 0; st >>= 1) { if (t < st) red[t] += red[t+st]; __syncthreads(); }
    if (t == 0) {
        out[LOSS_OFF] = 1.25f * g_loss_sum / (float)OUT_ELEMS;
        out[PERP_OFF] = expf(-red[0]);
    }
}

// ---------------------------------------------------------------------------
extern "C" void kernel_launch(void* const* d_in, const int* in_sizes, int n_in,
                              void* d_out, int out_size) {
    const float* z      = (const float*)d_in[0];
    const float* emb    = (const float*)d_in[1];
    const float* conv_w = (const float*)d_in[2];
    const float* conv_b = (const float*)d_in[3];
    float* out = (float*)d_out;

    cudaFuncSetAttribute(k_argmin_tc, cudaFuncAttributeMaxDynamicSharedMemorySize, DYN_SMEM);

    k_ee2_reset<<<NE, 256>>>(emb);
    k_esplit<<<NCHUNK, 256>>>(emb);
    k_codeout<<<dim3(CC/64, NE/64), 256>>>(emb, conv_w, conv_b);
    k_argmin_tc<<<NPIX/128, 256, DYN_SMEM>>>(z, out);
    k_scatter<<<BB*HH, 256>>>(out);
    k_finalize<<<1, 256>>>(out);
}

// round 11
// speedup vs baseline: 2.5865x; 1.0493x over previous
#include <cuda_runtime.h>
#include <cuda_bf16.h>
#include <math.h>
#include <stdint.h>

// Problem constants
#define BB   16
#define CC   1024
#define HH   32
#define WW   32
#define NE   256
#define NPIX (BB*HH*WW)          // 16384
#define OUT_ELEMS (BB*CC*HH*WW)  // 16777216
#define LOSS_OFF  OUT_ELEMS
#define PERP_OFF  (OUT_ELEMS+1)
#define IDX_OFF   (OUT_ELEMS+2)

#define KCHUNK 32
#define NCHUNK (CC/KCHUNK)       // 32

// Scratch (no cudaMalloc allowed)
__device__ float g_code_out[CC*NE];   // TRANSPOSED: [o][j]
__device__ float g_ee2[NE];
__device__ int   g_idx[NPIX];
__device__ int   g_counts[NE];
__device__ float g_loss_sum;
// e splits (tf32 bit patterns), pre-permuted into m16n8k8 B-fragment order:
// [split(2)][chunk(32)][kt(4)][nt(32)][lane(32)][slot(2)]  = 2 MB
#define CHW 8192   // words per (split,chunk) plane
__device__ __align__(16) float g_es2[2*NCHUNK*CHW];

// ---------------------------------------------------------------------------
__device__ __forceinline__ uint32_t f2tf32(float x) {
    uint32_t r;
    asm("cvt.rna.tf32.f32 %0, %1;" : "=r"(r) : "f"(x));
    return r;
}
__device__ __forceinline__ void mma_tf32(float c[4],
    uint32_t a0, uint32_t a1, uint32_t a2, uint32_t a3,
    uint32_t b0, uint32_t b1)
{
    asm volatile(
        "mma.sync.aligned.m16n8k8.row.col.f32.tf32.tf32.f32 "
        "{%0,%1,%2,%3}, {%4,%5,%6,%7}, {%8,%9}, {%0,%1,%2,%3};"
        : "+f"(c[0]), "+f"(c[1]), "+f"(c[2]), "+f"(c[3])
        : "r"(a0), "r"(a1), "r"(a2), "r"(a3), "r"(b0), "r"(b1));
}
__device__ __forceinline__ uint32_t smem_u32(const void* p) {
    uint32_t a;
    asm("{ .reg .u64 t; cvta.to.shared.u64 t, %1; cvt.u32.u64 %0, t; }" : "=r"(a) : "l"(p));
    return a;
}
__device__ __forceinline__ void cp_async16(uint32_t saddr, const void* g) {
    asm volatile("cp.async.cg.shared.global [%0], [%1], 16;" :: "r"(saddr), "l"(g));
}
#define CP_COMMIT() asm volatile("cp.async.commit_group;")
#define CP_WAIT0()  asm volatile("cp.async.wait_group 0;" ::: "memory")

// ---------------------------------------------------------------------------
// Kernel 0 (merged): |e_j|^2 + reset accumulators + 2-way tf32 split of emb
// into B-fragment-permuted g_es2. One block per code j.
// ---------------------------------------------------------------------------
__global__ void k_prep(const float* __restrict__ emb) {
    int j = blockIdx.x, t = threadIdx.x;   // 256 x 256
    int nt = j >> 3;
    float s = 0.f;
    #pragma unroll
    for (int i = 0; i < 4; i++) {
        int k = t*4 + i;
        float x = emb[(size_t)j*CC + k];
        s = fmaf(x, x, s);
        uint32_t hi = f2tf32(x);
        uint32_t lo = f2tf32(x - __uint_as_float(hi));
        int ch = k >> 5, kk5 = k & 31;
        int kt = kk5 >> 3, kk = kk5 & 7;
        int lane = (j & 7)*4 + (kk & 3);
        int slot = kk >> 2;
        size_t off = (((size_t)kt*32 + nt)*32 + lane)*2 + slot;
        ((uint32_t*)g_es2)[(size_t)ch*CHW + off] = hi;
        ((uint32_t*)g_es2)[(size_t)(NCHUNK + ch)*CHW + off] = lo;
    }
    __shared__ float red[256];
    red[t] = s; __syncthreads();
    for (int st = 128; st > 0; st >>= 1) { if (t < st) red[t] += red[t+st]; __syncthreads(); }
    if (t == 0) { g_ee2[j] = red[0]; g_counts[j] = 0; if (j == 0) g_loss_sum = 0.f; }
}

// ---------------------------------------------------------------------------
// Kernel 1: code_out[o][j] = emb[j].conv_w[o] + b[o]   (fp32, transposed out)
// ---------------------------------------------------------------------------
__global__ void __launch_bounds__(256) k_codeout(
    const float* __restrict__ emb, const float* __restrict__ w,
    const float* __restrict__ bias)
{
    __shared__ float es[16][64];
    __shared__ float ws[16][64];
    int t  = threadIdx.x;
    int o0 = blockIdx.x * 64, j0 = blockIdx.y * 64;
    int rl = t & 63, grp = t >> 6;
    int tol = t & 15, tjl = t >> 4;
    float acc[4][4] = {};
    for (int k0 = 0; k0 < CC; k0 += 16) {
        float4 fe = *(const float4*)&emb[(size_t)(j0+rl)*CC + k0 + grp*4];
        float4 fw = *(const float4*)&w  [(size_t)(o0+rl)*CC + k0 + grp*4];
        es[grp*4+0][rl]=fe.x; es[grp*4+1][rl]=fe.y; es[grp*4+2][rl]=fe.z; es[grp*4+3][rl]=fe.w;
        ws[grp*4+0][rl]=fw.x; ws[grp*4+1][rl]=fw.y; ws[grp*4+2][rl]=fw.z; ws[grp*4+3][rl]=fw.w;
        __syncthreads();
        #pragma unroll
        for (int kk = 0; kk < 16; kk++) {
            float er[4], wr[4];
            #pragma unroll
            for (int i = 0; i < 4; i++) { er[i] = es[kk][tjl*4+i]; wr[i] = ws[kk][tol*4+i]; }
            #pragma unroll
            for (int jy = 0; jy < 4; jy++)
                #pragma unroll
                for (int ox = 0; ox < 4; ox++)
                    acc[jy][ox] = fmaf(er[jy], wr[ox], acc[jy][ox]);
        }
        __syncthreads();
    }
    #pragma unroll
    for (int jy = 0; jy < 4; jy++)
        #pragma unroll
        for (int ox = 0; ox < 4; ox++)
            g_code_out[(size_t)(o0+tol*4+ox)*NE + (j0+tjl*4+jy)] = acc[jy][ox] + bias[o0+tol*4+ox];
}

// ---------------------------------------------------------------------------
// Kernel 2: 3xTF32 warp-MMA argmin, cp.async double-buffered, KCHUNK=32,
// cvt interleaved into compute. 128 CTAs x 256 thr (warp grid 2x4).
// ---------------------------------------------------------------------------
// Per buffer: A = 2 planes x 4096 fl (32KB), B = 2 splits x 8192 fl (64KB)
#define A_BUF 8192
#define B_BUF 16384
#define DYN_SMEM ((2*A_BUF + 2*B_BUF) * 4)   // 192 KB

__global__ void __launch_bounds__(256, 1) k_argmin_tc(
    const float* __restrict__ z, float* __restrict__ out)
{
    extern __shared__ float smem[];
    float* As = smem;                  // 2 x A_BUF
    float* Bs = smem + 2*A_BUF;        // 2 x B_BUF
    __shared__ unsigned long long sKey[128];
    __shared__ float redf[256];
    __shared__ float ee2_s[NE];

    int t = threadIdx.x, lane = t & 31, w = t >> 5;
    int wm = w >> 2, wn = w & 3;         // warp grid 2 (M) x 4 (N)
    int g = lane >> 2, tig = lane & 3;
    int cta = blockIdx.x;                // 128 CTAs
    int bb = cta >> 3;
    int p0 = (cta & 7) * 128;

    if (t < 128) sKey[t] = ~0ull;
    ee2_s[t] = g_ee2[t];

    uint32_t bs_addr = smem_u32(Bs);

    float acc[4][8][4];
    #pragma unroll
    for (int m = 0; m < 4; m++)
        #pragma unroll
        for (int n = 0; n < 8; n++)
            #pragma unroll
            for (int q = 0; q < 4; q++) acc[m][n][q] = 0.f;

    float zsq = 0.f;
    const float* zb = z + (size_t)bb*(CC*1024) + p0;

    // A tiles: 32 (kt4 x mt8) per chunk; warp w owns tiles w*4..w*4+3.
    int kt_a[4], mt_a[4];
    #pragma unroll
    for (int i = 0; i < 4; i++) { int tile = w*4 + i; kt_a[i] = tile >> 3; mt_a[i] = tile & 7; }

    float zr[8];   // prefetch registers: one half (2 tiles) at a time

    auto ld_a = [&](int ch, int half) {
        #pragma unroll
        for (int i = 0; i < 2; i++) {
            int ti = half*2 + i;
            const float* zp = zb + (size_t)(ch*KCHUNK + kt_a[ti]*8 + tig)*1024 + mt_a[ti]*16 + g;
            zr[i*4+0] = zp[0];
            zr[i*4+1] = zp[8];
            zr[i*4+2] = zp[4*1024];
            zr[i*4+3] = zp[4*1024 + 8];
        }
    };
    auto cvt_a = [&](int buf, int half) {
        #pragma unroll
        for (int i = 0; i < 2; i++) {
            int ti = half*2 + i;
            float v0 = zr[i*4+0], v1 = zr[i*4+1], v2 = zr[i*4+2], v3 = zr[i*4+3];
            zsq = fmaf(v0,v0,zsq); zsq = fmaf(v1,v1,zsq);
            zsq = fmaf(v2,v2,zsq); zsq = fmaf(v3,v3,zsq);
            uint32_t h0=f2tf32(v0), h1=f2tf32(v1), h2=f2tf32(v2), h3=f2tf32(v3);
            uint32_t l0=f2tf32(v0-__uint_as_float(h0));
            uint32_t l1=f2tf32(v1-__uint_as_float(h1));
            uint32_t l2=f2tf32(v2-__uint_as_float(h2));
            uint32_t l3=f2tf32(v3-__uint_as_float(h3));
            int base = buf*A_BUF + ((kt_a[ti]*8 + mt_a[ti])*32 + lane)*4;
            *(uint4*)&As[base]        = make_uint4(h0,h1,h2,h3);
            *(uint4*)&As[base + 4096] = make_uint4(l0,l1,l2,l3);
        }
    };
    auto issue_b = [&](int ch, int buf) {
        const float* s0 = g_es2 + (size_t)ch*CHW;
        const float* s1 = g_es2 + (size_t)(NCHUNK + ch)*CHW;
        uint32_t d0 = bs_addr + (buf*B_BUF)*4;
        uint32_t d1 = d0 + 8192*4;
        #pragma unroll
        for (int q = 0; q < 8; q++) {
            int idx = t + 256*q;
            cp_async16(d0 + idx*16, (const void*)(s0 + idx*4));
            cp_async16(d1 + idx*16, (const void*)(s1 + idx*4));
        }
    };
    auto compute = [&](int buf, int ktlo) {
        #pragma unroll
        for (int kk = 0; kk < 2; kk++) {
            int kt = ktlo + kk;
            uint4 ah[4], al[4];
            #pragma unroll
            for (int m = 0; m < 4; m++) {
                int base = buf*A_BUF + ((kt*8 + wm*4 + m)*32 + lane)*4;
                ah[m] = *(const uint4*)&As[base];
                al[m] = *(const uint4*)&As[base + 4096];
            }
            #pragma unroll
            for (int n = 0; n < 8; n++) {
                int bbase = buf*B_BUF + ((kt*32 + wn*8 + n)*32 + lane)*2;
                uint2 bh = *(const uint2*)&Bs[bbase];
                uint2 bl = *(const uint2*)&Bs[bbase + 8192];
                #pragma unroll
                for (int m = 0; m < 4; m++) {
                    mma_tf32(acc[m][n], ah[m].x, ah[m].y, ah[m].z, ah[m].w, bh.x, bh.y);
                    mma_tf32(acc[m][n], ah[m].x, ah[m].y, ah[m].z, ah[m].w, bl.x, bl.y);
                    mma_tf32(acc[m][n], al[m].x, al[m].y, al[m].z, al[m].w, bh.x, bh.y);
                }
            }
        }
    };

    // --- prologue: stage chunk 0 into buffer 0 ---
    issue_b(0, 0);
    CP_COMMIT();
    ld_a(0, 0); cvt_a(0, 0);
    ld_a(0, 1); cvt_a(0, 1);
    CP_WAIT0();
    __syncthreads();

    // --- main pipeline: cvt of next chunk interleaved between kt halves ---
    for (int ch = 0; ch < NCHUNK; ch++) {
        int buf = ch & 1, nbuf = buf ^ 1;
        bool more = (ch + 1 < NCHUNK);
        if (more) {
            issue_b(ch + 1, nbuf);
            CP_COMMIT();
            ld_a(ch + 1, 0);
        }
        compute(buf, 0);
        if (more) {
            cvt_a(nbuf, 0);
            ld_a(ch + 1, 1);
        }
        compute(buf, 2);
        if (more) {
            cvt_a(nbuf, 1);
            CP_WAIT0();
        }
        __syncthreads();
    }

    // --- epilogue: per-thread min over its 16 codes for each of 8 pixels ---
    #pragma unroll
    for (int m = 0; m < 4; m++) {
        unsigned long long b0 = ~0ull, b1 = ~0ull;
        #pragma unroll
        for (int n = 0; n < 8; n++) {
            int j0 = wn*64 + n*8 + tig*2;
            #pragma unroll
            for (int q = 0; q < 2; q++) {
                float s_lo = ee2_s[j0+q] - 2.f*acc[m][n][q];
                float s_hi = ee2_s[j0+q] - 2.f*acc[m][n][q+2];
                unsigned u0 = __float_as_uint(s_lo);
                u0 = (u0 & 0x80000000u) ? ~u0 : (u0 | 0x80000000u);
                unsigned long long k0 = ((unsigned long long)u0 << 32) | (unsigned)(j0+q);
                b0 = (k0 < b0) ? k0 : b0;
                unsigned u1 = __float_as_uint(s_hi);
                u1 = (u1 & 0x80000000u) ? ~u1 : (u1 | 0x80000000u);
                unsigned long long k1 = ((unsigned long long)u1 << 32) | (unsigned)(j0+q);
                b1 = (k1 < b1) ? k1 : b1;
            }
        }
        int prow = wm*64 + m*16 + g;
        atomicMin(&sKey[prow], b0);
        atomicMin(&sKey[prow + 8], b1);
    }
    __syncthreads();

    float dmin = 0.f;
    if (t < 128) {
        unsigned long long k = sKey[t];
        int j = (int)(k & 0xFFFFFFFFu);
        unsigned u = (unsigned)(k >> 32);
        unsigned fb = (u & 0x80000000u) ? (u & 0x7FFFFFFFu) : ~u;
        dmin = __uint_as_float(fb);
        int n = cta*128 + t;
        g_idx[n] = j;
        atomicAdd(&g_counts[j], 1);
        out[IDX_OFF + n] = (float)j;
    }

    redf[t] = zsq + dmin;
    __syncthreads();
    for (int st = 128; st > 0; st >>= 1) { if (t < st) redf[t] += redf[t+st]; __syncthreads(); }
    if (t == 0) atomicAdd(&g_loss_sum, redf[0]);
}

// ---------------------------------------------------------------------------
// Kernel 3: gather-scatter. out[b,o,h,w] = code_out[o][idx[b,h,w]].
// ---------------------------------------------------------------------------
__global__ void __launch_bounds__(256) k_scatter(float* __restrict__ out)
{
    int bid = blockIdx.x;
    int b  = bid >> 5, oc = bid & 31;
    __shared__ int   idx_s[1024];
    __shared__ float ct[32*256];
    int t = threadIdx.x;
    #pragma unroll
    for (int r = 0; r < 4; r++) idx_s[t + 256*r] = g_idx[b*1024 + t + 256*r];
    const float4* src = (const float4*)(g_code_out + (size_t)oc*32*NE);
    float4* dst = (float4*)ct;
    #pragma unroll
    for (int r = 0; r < 8; r++) dst[t + 256*r] = src[t + 256*r];
    __syncthreads();
    int warp = t >> 5, lane = t & 31;
    float* ob = out + (size_t)b*(CC*HH*WW) + (size_t)oc*32*(HH*WW);
    #pragma unroll
    for (int q = 0; q < 4; q++) {
        int o = warp*4 + q;
        const float* crow = &ct[o*NE];
        #pragma unroll
        for (int p0 = 0; p0 < 1024; p0 += 128) {
            int4 j4 = *(const int4*)&idx_s[p0 + lane*4];
            float4 v;
            v.x = crow[j4.x]; v.y = crow[j4.y]; v.z = crow[j4.z]; v.w = crow[j4.w];
            *(float4*)&ob[(size_t)o*(HH*WW) + p0 + lane*4] = v;
        }
    }
}

// ---------------------------------------------------------------------------
// Kernel 4: finalize loss + perplexity
// ---------------------------------------------------------------------------
__global__ void k_finalize(float* __restrict__ out) {
    int t = threadIdx.x;
    float em = (float)g_counts[t] / (float)NPIX;
    float term = em * logf(em + 1e-10f);
    __shared__ float red[256];
    red[t] = term; __syncthreads();
    for (int st = 128; st > 0; st >>= 1) { if (t < st) red[t] += red[t+st]; __syncthreads(); }
    if (t == 0) {
        out[LOSS_OFF] = 1.25f * g_loss_sum / (float)OUT_ELEMS;
        out[PERP_OFF] = expf(-red[0]);
    }
}

// ---------------------------------------------------------------------------
extern "C" void kernel_launch(void* const* d_in, const int* in_sizes, int n_in,
                              void* d_out, int out_size) {
    const float* z      = (const float*)d_in[0];
    const float* emb    = (const float*)d_in[1];
    const float* conv_w = (const float*)d_in[2];
    const float* conv_b = (const float*)d_in[3];
    float* out = (float*)d_out;

    cudaFuncSetAttribute(k_argmin_tc, cudaFuncAttributeMaxDynamicSharedMemorySize, DYN_SMEM);

    k_prep<<<NE, 256>>>(emb);
    k_codeout<<<dim3(CC/64, NE/64), 256>>>(emb, conv_w, conv_b);
    k_argmin_tc<<<NPIX/128, 256, DYN_SMEM>>>(z, out);
    k_scatter<<<BB*HH, 256>>>(out);
    k_finalize<<<1, 256>>>(out);
}

// round 12
// speedup vs baseline: 2.6250x; 1.0149x over previous
#include <cuda_runtime.h>
#include <cuda_bf16.h>
#include <math.h>
#include <stdint.h>

// Problem constants
#define BB   16
#define CC   1024
#define HH   32
#define WW   32
#define NE   256
#define NPIX (BB*HH*WW)          // 16384
#define OUT_ELEMS (BB*CC*HH*WW)  // 16777216
#define LOSS_OFF  OUT_ELEMS
#define PERP_OFF  (OUT_ELEMS+1)
#define IDX_OFF   (OUT_ELEMS+2)

#define KCHUNK 32
#define NCHUNK (CC/KCHUNK)       // 32

// Scratch (no cudaMalloc allowed)
__device__ float g_code_out[CC*NE];   // TRANSPOSED: [o][j]
__device__ float g_ee2[NE];
__device__ int   g_idx[NPIX];
__device__ int   g_counts[NE];
__device__ float g_loss_sum;
// e splits (tf32 bit patterns), pre-permuted into m16n8k8 B-fragment order:
// [split(2)][chunk(32)][kt(4)][nt(32)][lane(32)][slot(2)]  = 2 MB
#define CHW 8192   // words per (split,chunk) plane
__device__ __align__(16) float g_es2[2*NCHUNK*CHW];

// ---------------------------------------------------------------------------
__device__ __forceinline__ uint32_t f2tf32(float x) {
    uint32_t r;
    asm("cvt.rna.tf32.f32 %0, %1;" : "=r"(r) : "f"(x));
    return r;
}
__device__ __forceinline__ void mma_tf32(float c[4],
    uint32_t a0, uint32_t a1, uint32_t a2, uint32_t a3,
    uint32_t b0, uint32_t b1)
{
    asm volatile(
        "mma.sync.aligned.m16n8k8.row.col.f32.tf32.tf32.f32 "
        "{%0,%1,%2,%3}, {%4,%5,%6,%7}, {%8,%9}, {%0,%1,%2,%3};"
        : "+f"(c[0]), "+f"(c[1]), "+f"(c[2]), "+f"(c[3])
        : "r"(a0), "r"(a1), "r"(a2), "r"(a3), "r"(b0), "r"(b1));
}
__device__ __forceinline__ uint32_t smem_u32(const void* p) {
    uint32_t a;
    asm("{ .reg .u64 t; cvta.to.shared.u64 t, %1; cvt.u32.u64 %0, t; }" : "=r"(a) : "l"(p));
    return a;
}
__device__ __forceinline__ void cp_async16(uint32_t saddr, const void* g) {
    asm volatile("cp.async.cg.shared.global [%0], [%1], 16;" :: "r"(saddr), "l"(g));
}
#define CP_COMMIT() asm volatile("cp.async.commit_group;")
#define CP_WAIT0()  asm volatile("cp.async.wait_group 0;" ::: "memory")

// ---------------------------------------------------------------------------
// Kernel 0 (merged): |e_j|^2 + reset accumulators + 2-way tf32 split of emb
// into B-fragment-permuted g_es2. One block per code j.
// ---------------------------------------------------------------------------
__global__ void k_prep(const float* __restrict__ emb) {
    int j = blockIdx.x, t = threadIdx.x;   // 256 x 256
    int nt = j >> 3;
    float s = 0.f;
    #pragma unroll
    for (int i = 0; i < 4; i++) {
        int k = t*4 + i;
        float x = emb[(size_t)j*CC + k];
        s = fmaf(x, x, s);
        uint32_t hi = f2tf32(x);
        uint32_t lo = f2tf32(x - __uint_as_float(hi));
        int ch = k >> 5, kk5 = k & 31;
        int kt = kk5 >> 3, kk = kk5 & 7;
        int lane = (j & 7)*4 + (kk & 3);
        int slot = kk >> 2;
        size_t off = (((size_t)kt*32 + nt)*32 + lane)*2 + slot;
        ((uint32_t*)g_es2)[(size_t)ch*CHW + off] = hi;
        ((uint32_t*)g_es2)[(size_t)(NCHUNK + ch)*CHW + off] = lo;
    }
    __shared__ float red[256];
    red[t] = s; __syncthreads();
    for (int st = 128; st > 0; st >>= 1) { if (t < st) red[t] += red[t+st]; __syncthreads(); }
    if (t == 0) { g_ee2[j] = red[0]; g_counts[j] = 0; if (j == 0) g_loss_sum = 0.f; }
}

// ---------------------------------------------------------------------------
// Kernel 1: code_out[o][j] = emb[j].conv_w[o] + b[o]   (fp32, transposed out)
// Runs CONCURRENTLY with k_prep/k_argmin_tc on a forked stream.
// ---------------------------------------------------------------------------
__global__ void __launch_bounds__(256) k_codeout(
    const float* __restrict__ emb, const float* __restrict__ w,
    const float* __restrict__ bias)
{
    __shared__ float es[16][64];
    __shared__ float ws[16][64];
    int t  = threadIdx.x;
    int o0 = blockIdx.x * 64, j0 = blockIdx.y * 64;
    int rl = t & 63, grp = t >> 6;
    int tol = t & 15, tjl = t >> 4;
    float acc[4][4] = {};
    for (int k0 = 0; k0 < CC; k0 += 16) {
        float4 fe = *(const float4*)&emb[(size_t)(j0+rl)*CC + k0 + grp*4];
        float4 fw = *(const float4*)&w  [(size_t)(o0+rl)*CC + k0 + grp*4];
        es[grp*4+0][rl]=fe.x; es[grp*4+1][rl]=fe.y; es[grp*4+2][rl]=fe.z; es[grp*4+3][rl]=fe.w;
        ws[grp*4+0][rl]=fw.x; ws[grp*4+1][rl]=fw.y; ws[grp*4+2][rl]=fw.z; ws[grp*4+3][rl]=fw.w;
        __syncthreads();
        #pragma unroll
        for (int kk = 0; kk < 16; kk++) {
            float er[4], wr[4];
            #pragma unroll
            for (int i = 0; i < 4; i++) { er[i] = es[kk][tjl*4+i]; wr[i] = ws[kk][tol*4+i]; }
            #pragma unroll
            for (int jy = 0; jy < 4; jy++)
                #pragma unroll
                for (int ox = 0; ox < 4; ox++)
                    acc[jy][ox] = fmaf(er[jy], wr[ox], acc[jy][ox]);
        }
        __syncthreads();
    }
    #pragma unroll
    for (int jy = 0; jy < 4; jy++)
        #pragma unroll
        for (int ox = 0; ox < 4; ox++)
            g_code_out[(size_t)(o0+tol*4+ox)*NE + (j0+tjl*4+jy)] = acc[jy][ox] + bias[o0+tol*4+ox];
}

// ---------------------------------------------------------------------------
// Kernel 2: 3xTF32 warp-MMA argmin, cp.async double-buffered, KCHUNK=32,
// cvt interleaved into compute. 128 CTAs x 256 thr (warp grid 2x4).
// ---------------------------------------------------------------------------
// Per buffer: A = 2 planes x 4096 fl (32KB), B = 2 splits x 8192 fl (64KB)
#define A_BUF 8192
#define B_BUF 16384
#define DYN_SMEM ((2*A_BUF + 2*B_BUF) * 4)   // 192 KB

__global__ void __launch_bounds__(256, 1) k_argmin_tc(
    const float* __restrict__ z, float* __restrict__ out)
{
    extern __shared__ float smem[];
    float* As = smem;                  // 2 x A_BUF
    float* Bs = smem + 2*A_BUF;        // 2 x B_BUF
    __shared__ unsigned long long sKey[128];
    __shared__ float redf[256];
    __shared__ float ee2_s[NE];

    int t = threadIdx.x, lane = t & 31, w = t >> 5;
    int wm = w >> 2, wn = w & 3;         // warp grid 2 (M) x 4 (N)
    int g = lane >> 2, tig = lane & 3;
    int cta = blockIdx.x;                // 128 CTAs
    int bb = cta >> 3;
    int p0 = (cta & 7) * 128;

    if (t < 128) sKey[t] = ~0ull;
    ee2_s[t] = g_ee2[t];

    uint32_t bs_addr = smem_u32(Bs);

    float acc[4][8][4];
    #pragma unroll
    for (int m = 0; m < 4; m++)
        #pragma unroll
        for (int n = 0; n < 8; n++)
            #pragma unroll
            for (int q = 0; q < 4; q++) acc[m][n][q] = 0.f;

    float zsq = 0.f;
    const float* zb = z + (size_t)bb*(CC*1024) + p0;

    // A tiles: 32 (kt4 x mt8) per chunk; warp w owns tiles w*4..w*4+3.
    int kt_a[4], mt_a[4];
    #pragma unroll
    for (int i = 0; i < 4; i++) { int tile = w*4 + i; kt_a[i] = tile >> 3; mt_a[i] = tile & 7; }

    float zr[8];   // prefetch registers: one half (2 tiles) at a time

    auto ld_a = [&](int ch, int half) {
        #pragma unroll
        for (int i = 0; i < 2; i++) {
            int ti = half*2 + i;
            const float* zp = zb + (size_t)(ch*KCHUNK + kt_a[ti]*8 + tig)*1024 + mt_a[ti]*16 + g;
            zr[i*4+0] = zp[0];
            zr[i*4+1] = zp[8];
            zr[i*4+2] = zp[4*1024];
            zr[i*4+3] = zp[4*1024 + 8];
        }
    };
    auto cvt_a = [&](int buf, int half) {
        #pragma unroll
        for (int i = 0; i < 2; i++) {
            int ti = half*2 + i;
            float v0 = zr[i*4+0], v1 = zr[i*4+1], v2 = zr[i*4+2], v3 = zr[i*4+3];
            zsq = fmaf(v0,v0,zsq); zsq = fmaf(v1,v1,zsq);
            zsq = fmaf(v2,v2,zsq); zsq = fmaf(v3,v3,zsq);
            uint32_t h0=f2tf32(v0), h1=f2tf32(v1), h2=f2tf32(v2), h3=f2tf32(v3);
            uint32_t l0=f2tf32(v0-__uint_as_float(h0));
            uint32_t l1=f2tf32(v1-__uint_as_float(h1));
            uint32_t l2=f2tf32(v2-__uint_as_float(h2));
            uint32_t l3=f2tf32(v3-__uint_as_float(h3));
            int base = buf*A_BUF + ((kt_a[ti]*8 + mt_a[ti])*32 + lane)*4;
            *(uint4*)&As[base]        = make_uint4(h0,h1,h2,h3);
            *(uint4*)&As[base + 4096] = make_uint4(l0,l1,l2,l3);
        }
    };
    auto issue_b = [&](int ch, int buf) {
        const float* s0 = g_es2 + (size_t)ch*CHW;
        const float* s1 = g_es2 + (size_t)(NCHUNK + ch)*CHW;
        uint32_t d0 = bs_addr + (buf*B_BUF)*4;
        uint32_t d1 = d0 + 8192*4;
        #pragma unroll
        for (int q = 0; q < 8; q++) {
            int idx = t + 256*q;
            cp_async16(d0 + idx*16, (const void*)(s0 + idx*4));
            cp_async16(d1 + idx*16, (const void*)(s1 + idx*4));
        }
    };
    auto compute = [&](int buf, int ktlo) {
        #pragma unroll
        for (int kk = 0; kk < 2; kk++) {
            int kt = ktlo + kk;
            uint4 ah[4], al[4];
            #pragma unroll
            for (int m = 0; m < 4; m++) {
                int base = buf*A_BUF + ((kt*8 + wm*4 + m)*32 + lane)*4;
                ah[m] = *(const uint4*)&As[base];
                al[m] = *(const uint4*)&As[base + 4096];
            }
            #pragma unroll
            for (int n = 0; n < 8; n++) {
                int bbase = buf*B_BUF + ((kt*32 + wn*8 + n)*32 + lane)*2;
                uint2 bh = *(const uint2*)&Bs[bbase];
                uint2 bl = *(const uint2*)&Bs[bbase + 8192];
                #pragma unroll
                for (int m = 0; m < 4; m++) {
                    mma_tf32(acc[m][n], ah[m].x, ah[m].y, ah[m].z, ah[m].w, bh.x, bh.y);
                    mma_tf32(acc[m][n], ah[m].x, ah[m].y, ah[m].z, ah[m].w, bl.x, bl.y);
                    mma_tf32(acc[m][n], al[m].x, al[m].y, al[m].z, al[m].w, bh.x, bh.y);
                }
            }
        }
    };

    // --- prologue: stage chunk 0 into buffer 0 ---
    issue_b(0, 0);
    CP_COMMIT();
    ld_a(0, 0); cvt_a(0, 0);
    ld_a(0, 1); cvt_a(0, 1);
    CP_WAIT0();
    __syncthreads();

    // --- main pipeline: cvt of next chunk interleaved between kt halves ---
    for (int ch = 0; ch < NCHUNK; ch++) {
        int buf = ch & 1, nbuf = buf ^ 1;
        bool more = (ch + 1 < NCHUNK);
        if (more) {
            issue_b(ch + 1, nbuf);
            CP_COMMIT();
            ld_a(ch + 1, 0);
        }
        compute(buf, 0);
        if (more) {
            cvt_a(nbuf, 0);
            ld_a(ch + 1, 1);
        }
        compute(buf, 2);
        if (more) {
            cvt_a(nbuf, 1);
            CP_WAIT0();
        }
        __syncthreads();
    }

    // --- epilogue: per-thread min over its 16 codes for each of 8 pixels ---
    #pragma unroll
    for (int m = 0; m < 4; m++) {
        unsigned long long b0 = ~0ull, b1 = ~0ull;
        #pragma unroll
        for (int n = 0; n < 8; n++) {
            int j0 = wn*64 + n*8 + tig*2;
            #pragma unroll
            for (int q = 0; q < 2; q++) {
                float s_lo = ee2_s[j0+q] - 2.f*acc[m][n][q];
                float s_hi = ee2_s[j0+q] - 2.f*acc[m][n][q+2];
                unsigned u0 = __float_as_uint(s_lo);
                u0 = (u0 & 0x80000000u) ? ~u0 : (u0 | 0x80000000u);
                unsigned long long k0 = ((unsigned long long)u0 << 32) | (unsigned)(j0+q);
                b0 = (k0 < b0) ? k0 : b0;
                unsigned u1 = __float_as_uint(s_hi);
                u1 = (u1 & 0x80000000u) ? ~u1 : (u1 | 0x80000000u);
                unsigned long long k1 = ((unsigned long long)u1 << 32) | (unsigned)(j0+q);
                b1 = (k1 < b1) ? k1 : b1;
            }
        }
        int prow = wm*64 + m*16 + g;
        atomicMin(&sKey[prow], b0);
        atomicMin(&sKey[prow + 8], b1);
    }
    __syncthreads();

    float dmin = 0.f;
    if (t < 128) {
        unsigned long long k = sKey[t];
        int j = (int)(k & 0xFFFFFFFFu);
        unsigned u = (unsigned)(k >> 32);
        unsigned fb = (u & 0x80000000u) ? (u & 0x7FFFFFFFu) : ~u;
        dmin = __uint_as_float(fb);
        int n = cta*128 + t;
        g_idx[n] = j;
        atomicAdd(&g_counts[j], 1);
        out[IDX_OFF + n] = (float)j;
    }

    redf[t] = zsq + dmin;
    __syncthreads();
    for (int st = 128; st > 0; st >>= 1) { if (t < st) redf[t] += redf[t+st]; __syncthreads(); }
    if (t == 0) atomicAdd(&g_loss_sum, redf[0]);
}

// ---------------------------------------------------------------------------
// Kernel 3: gather-scatter. out[b,o,h,w] = code_out[o][idx[b,h,w]].
// ---------------------------------------------------------------------------
__global__ void __launch_bounds__(256) k_scatter(float* __restrict__ out)
{
    int bid = blockIdx.x;
    int b  = bid >> 5, oc = bid & 31;
    __shared__ int   idx_s[1024];
    __shared__ float ct[32*256];
    int t = threadIdx.x;
    #pragma unroll
    for (int r = 0; r < 4; r++) idx_s[t + 256*r] = g_idx[b*1024 + t + 256*r];
    const float4* src = (const float4*)(g_code_out + (size_t)oc*32*NE);
    float4* dst = (float4*)ct;
    #pragma unroll
    for (int r = 0; r < 8; r++) dst[t + 256*r] = src[t + 256*r];
    __syncthreads();
    int warp = t >> 5, lane = t & 31;
    float* ob = out + (size_t)b*(CC*HH*WW) + (size_t)oc*32*(HH*WW);
    #pragma unroll
    for (int q = 0; q < 4; q++) {
        int o = warp*4 + q;
        const float* crow = &ct[o*NE];
        #pragma unroll
        for (int p0 = 0; p0 < 1024; p0 += 128) {
            int4 j4 = *(const int4*)&idx_s[p0 + lane*4];
            float4 v;
            v.x = crow[j4.x]; v.y = crow[j4.y]; v.z = crow[j4.z]; v.w = crow[j4.w];
            *(float4*)&ob[(size_t)o*(HH*WW) + p0 + lane*4] = v;
        }
    }
}

// ---------------------------------------------------------------------------
// Kernel 4: finalize loss + perplexity
// ---------------------------------------------------------------------------
__global__ void k_finalize(float* __restrict__ out) {
    int t = threadIdx.x;
    float em = (float)g_counts[t] / (float)NPIX;
    float term = em * logf(em + 1e-10f);
    __shared__ float red[256];
    red[t] = term; __syncthreads();
    for (int st = 128; st > 0; st >>= 1) { if (t < st) red[t] += red[t+st]; __syncthreads(); }
    if (t == 0) {
        out[LOSS_OFF] = 1.25f * g_loss_sum / (float)OUT_ELEMS;
        out[PERP_OFF] = expf(-red[0]);
    }
}

// ---------------------------------------------------------------------------
// Launch: fork k_codeout onto a side stream (independent of prep/argmin),
// join before k_scatter. Cross-stream events become graph edges under capture.
// Stream/event handles are created lazily once (not device memory).
// ---------------------------------------------------------------------------
extern "C" void kernel_launch(void* const* d_in, const int* in_sizes, int n_in,
                              void* d_out, int out_size) {
    const float* z      = (const float*)d_in[0];
    const float* emb    = (const float*)d_in[1];
    const float* conv_w = (const float*)d_in[2];
    const float* conv_b = (const float*)d_in[3];
    float* out = (float*)d_out;

    static cudaStream_t s_side = 0;
    static cudaEvent_t  ev_fork = 0, ev_join = 0;
    if (s_side == 0) {
        cudaStreamCreateWithFlags(&s_side, cudaStreamNonBlocking);
        cudaEventCreateWithFlags(&ev_fork, cudaEventDisableTiming);
        cudaEventCreateWithFlags(&ev_join, cudaEventDisableTiming);
        cudaFuncSetAttribute(k_argmin_tc, cudaFuncAttributeMaxDynamicSharedMemorySize, DYN_SMEM);
    }

    // fork: side stream depends on stream-0 front
    cudaEventRecord(ev_fork, 0);
    cudaStreamWaitEvent(s_side, ev_fork, 0);

    // side stream: codeout (needs only emb, conv_w, conv_b)
    k_codeout<<<dim3(CC/64, NE/64), 256, 0, s_side>>>(emb, conv_w, conv_b);
    cudaEventRecord(ev_join, s_side);

    // main stream: prep -> argmin
    k_prep<<<NE, 256>>>(emb);
    k_argmin_tc<<<NPIX/128, 256, DYN_SMEM>>>(z, out);

    // join: scatter needs g_idx (main) + g_code_out (side)
    cudaStreamWaitEvent(0, ev_join, 0);
    k_scatter<<<BB*HH, 256>>>(out);
    k_finalize<<<1, 256>>>(out);
}

// round 13
// speedup vs baseline: 2.6555x; 1.0116x over previous
#include <cuda_runtime.h>
#include <cuda_bf16.h>
#include <math.h>
#include <stdint.h>

// Problem constants
#define BB   16
#define CC   1024
#define HH   32
#define WW   32
#define NE   256
#define NPIX (BB*HH*WW)          // 16384
#define OUT_ELEMS (BB*CC*HH*WW)  // 16777216
#define LOSS_OFF  OUT_ELEMS
#define PERP_OFF  (OUT_ELEMS+1)
#define IDX_OFF   (OUT_ELEMS+2)

#define KCHUNK 32
#define NCHUNK (CC/KCHUNK)       // 32

// Scratch (no cudaMalloc allowed)
__device__ float g_code_out[CC*NE];   // TRANSPOSED: [o][j]
__device__ float g_ee2[NE];
__device__ int   g_idx[NPIX];
__device__ int   g_counts[NE];
__device__ float g_loss_sum;
// e splits (tf32 bit patterns), pre-permuted into m16n8k8 B-fragment order:
// [split(2)][chunk(32)][kt(4)][nt(32)][lane(32)][slot(2)]  = 2 MB
#define CHW 8192   // words per (split,chunk) plane
__device__ __align__(16) float g_es2[2*NCHUNK*CHW];

// ---------------------------------------------------------------------------
__device__ __forceinline__ uint32_t f2tf32(float x) {
    uint32_t r;
    asm("cvt.rna.tf32.f32 %0, %1;" : "=r"(r) : "f"(x));
    return r;
}
__device__ __forceinline__ void mma_tf32(float c[4],
    uint32_t a0, uint32_t a1, uint32_t a2, uint32_t a3,
    uint32_t b0, uint32_t b1)
{
    asm volatile(
        "mma.sync.aligned.m16n8k8.row.col.f32.tf32.tf32.f32 "
        "{%0,%1,%2,%3}, {%4,%5,%6,%7}, {%8,%9}, {%0,%1,%2,%3};"
        : "+f"(c[0]), "+f"(c[1]), "+f"(c[2]), "+f"(c[3])
        : "r"(a0), "r"(a1), "r"(a2), "r"(a3), "r"(b0), "r"(b1));
}
__device__ __forceinline__ uint32_t smem_u32(const void* p) {
    uint32_t a;
    asm("{ .reg .u64 t; cvta.to.shared.u64 t, %1; cvt.u32.u64 %0, t; }" : "=r"(a) : "l"(p));
    return a;
}
__device__ __forceinline__ void cp_async16(uint32_t saddr, const void* g) {
    asm volatile("cp.async.cg.shared.global [%0], [%1], 16;" :: "r"(saddr), "l"(g));
}
#define CP_COMMIT() asm volatile("cp.async.commit_group;")
#define CP_WAIT0()  asm volatile("cp.async.wait_group 0;" ::: "memory")

// ---------------------------------------------------------------------------
// Kernel 0 (merged): |e_j|^2 + reset accumulators + 2-way tf32 split of emb
// into B-fragment-permuted g_es2. One block per code j.
// ---------------------------------------------------------------------------
__global__ void k_prep(const float* __restrict__ emb) {
    int j = blockIdx.x, t = threadIdx.x;   // 256 x 256
    int nt = j >> 3;
    float s = 0.f;
    #pragma unroll
    for (int i = 0; i < 4; i++) {
        int k = t*4 + i;
        float x = emb[(size_t)j*CC + k];
        s = fmaf(x, x, s);
        uint32_t hi = f2tf32(x);
        uint32_t lo = f2tf32(x - __uint_as_float(hi));
        int ch = k >> 5, kk5 = k & 31;
        int kt = kk5 >> 3, kk = kk5 & 7;
        int lane = (j & 7)*4 + (kk & 3);
        int slot = kk >> 2;
        size_t off = (((size_t)kt*32 + nt)*32 + lane)*2 + slot;
        ((uint32_t*)g_es2)[(size_t)ch*CHW + off] = hi;
        ((uint32_t*)g_es2)[(size_t)(NCHUNK + ch)*CHW + off] = lo;
    }
    __shared__ float red[256];
    red[t] = s; __syncthreads();
    for (int st = 128; st > 0; st >>= 1) { if (t < st) red[t] += red[t+st]; __syncthreads(); }
    if (t == 0) { g_ee2[j] = red[0]; g_counts[j] = 0; if (j == 0) g_loss_sum = 0.f; }
}

// ---------------------------------------------------------------------------
// Kernel 1: code_out[o][j] = emb[j].conv_w[o] + b[o]   (fp32, transposed out)
// Runs CONCURRENTLY with k_prep/k_argmin_tc on a forked stream.
// ---------------------------------------------------------------------------
__global__ void __launch_bounds__(256) k_codeout(
    const float* __restrict__ emb, const float* __restrict__ w,
    const float* __restrict__ bias)
{
    __shared__ float es[16][64];
    __shared__ float ws[16][64];
    int t  = threadIdx.x;
    int o0 = blockIdx.x * 64, j0 = blockIdx.y * 64;
    int rl = t & 63, grp = t >> 6;
    int tol = t & 15, tjl = t >> 4;
    float acc[4][4] = {};
    for (int k0 = 0; k0 < CC; k0 += 16) {
        float4 fe = *(const float4*)&emb[(size_t)(j0+rl)*CC + k0 + grp*4];
        float4 fw = *(const float4*)&w  [(size_t)(o0+rl)*CC + k0 + grp*4];
        es[grp*4+0][rl]=fe.x; es[grp*4+1][rl]=fe.y; es[grp*4+2][rl]=fe.z; es[grp*4+3][rl]=fe.w;
        ws[grp*4+0][rl]=fw.x; ws[grp*4+1][rl]=fw.y; ws[grp*4+2][rl]=fw.z; ws[grp*4+3][rl]=fw.w;
        __syncthreads();
        #pragma unroll
        for (int kk = 0; kk < 16; kk++) {
            float er[4], wr[4];
            #pragma unroll
            for (int i = 0; i < 4; i++) { er[i] = es[kk][tjl*4+i]; wr[i] = ws[kk][tol*4+i]; }
            #pragma unroll
            for (int jy = 0; jy < 4; jy++)
                #pragma unroll
                for (int ox = 0; ox < 4; ox++)
                    acc[jy][ox] = fmaf(er[jy], wr[ox], acc[jy][ox]);
        }
        __syncthreads();
    }
    #pragma unroll
    for (int jy = 0; jy < 4; jy++)
        #pragma unroll
        for (int ox = 0; ox < 4; ox++)
            g_code_out[(size_t)(o0+tol*4+ox)*NE + (j0+tjl*4+jy)] = acc[jy][ox] + bias[o0+tol*4+ox];
}

// ---------------------------------------------------------------------------
// Kernel 2: 3xTF32 warp-MMA argmin. 128 CTAs x 512 thr (16 warps, grid 4x4).
// Warp tile 32x64 -> 64-float acc, 4 warps/SMSP hides LDS/barrier latency.
// cp.async double-buffered, KCHUNK=32, cvt interleaved into compute.
// ---------------------------------------------------------------------------
// Per buffer: A = 2 planes x 4096 fl (32KB), B = 2 splits x 8192 fl (64KB)
#define A_BUF 8192
#define B_BUF 16384
#define DYN_SMEM ((2*A_BUF + 2*B_BUF) * 4)   // 192 KB

__global__ void __launch_bounds__(512, 1) k_argmin_tc(
    const float* __restrict__ z, float* __restrict__ out)
{
    extern __shared__ float smem[];
    float* As = smem;                  // 2 x A_BUF
    float* Bs = smem + 2*A_BUF;        // 2 x B_BUF
    __shared__ unsigned long long sKey[128];
    __shared__ float redf[512];
    __shared__ float ee2_s[NE];

    int t = threadIdx.x, lane = t & 31, w = t >> 5;
    int wm = w >> 2, wn = w & 3;         // warp grid 4 (M) x 4 (N)
    int g = lane >> 2, tig = lane & 3;
    int cta = blockIdx.x;                // 128 CTAs
    int bb = cta >> 3;
    int p0 = (cta & 7) * 128;

    if (t < 128) sKey[t] = ~0ull;
    if (t < NE)  ee2_s[t] = g_ee2[t];

    uint32_t bs_addr = smem_u32(Bs);

    float acc[2][8][4];
    #pragma unroll
    for (int m = 0; m < 2; m++)
        #pragma unroll
        for (int n = 0; n < 8; n++)
            #pragma unroll
            for (int q = 0; q < 4; q++) acc[m][n][q] = 0.f;

    float zsq = 0.f;
    const float* zb = z + (size_t)bb*(CC*1024) + p0;

    // A tiles: 32 (kt4 x mt8) per chunk; warp w owns tiles w*2, w*2+1.
    int kt_a[2], mt_a[2];
    #pragma unroll
    for (int i = 0; i < 2; i++) { int tile = w*2 + i; kt_a[i] = tile >> 3; mt_a[i] = tile & 7; }

    float zr[8];   // prefetch regs: tile 0 -> zr[0..3], tile 1 -> zr[4..7]

    auto ld_a = [&](int ch, int half) {
        const float* zp = zb + (size_t)(ch*KCHUNK + kt_a[half]*8 + tig)*1024 + mt_a[half]*16 + g;
        zr[half*4+0] = zp[0];
        zr[half*4+1] = zp[8];
        zr[half*4+2] = zp[4*1024];
        zr[half*4+3] = zp[4*1024 + 8];
    };
    auto cvt_a = [&](int buf, int half) {
        float v0 = zr[half*4+0], v1 = zr[half*4+1], v2 = zr[half*4+2], v3 = zr[half*4+3];
        zsq = fmaf(v0,v0,zsq); zsq = fmaf(v1,v1,zsq);
        zsq = fmaf(v2,v2,zsq); zsq = fmaf(v3,v3,zsq);
        uint32_t h0=f2tf32(v0), h1=f2tf32(v1), h2=f2tf32(v2), h3=f2tf32(v3);
        uint32_t l0=f2tf32(v0-__uint_as_float(h0));
        uint32_t l1=f2tf32(v1-__uint_as_float(h1));
        uint32_t l2=f2tf32(v2-__uint_as_float(h2));
        uint32_t l3=f2tf32(v3-__uint_as_float(h3));
        int base = buf*A_BUF + ((kt_a[half]*8 + mt_a[half])*32 + lane)*4;
        *(uint4*)&As[base]        = make_uint4(h0,h1,h2,h3);
        *(uint4*)&As[base + 4096] = make_uint4(l0,l1,l2,l3);
    };
    auto issue_b = [&](int ch, int buf) {
        const float* s0 = g_es2 + (size_t)ch*CHW;
        const float* s1 = g_es2 + (size_t)(NCHUNK + ch)*CHW;
        uint32_t d0 = bs_addr + (buf*B_BUF)*4;
        uint32_t d1 = d0 + 8192*4;
        #pragma unroll
        for (int q = 0; q < 4; q++) {
            int idx = t + 512*q;
            cp_async16(d0 + idx*16, (const void*)(s0 + idx*4));
            cp_async16(d1 + idx*16, (const void*)(s1 + idx*4));
        }
    };
    auto compute = [&](int buf, int ktlo) {
        #pragma unroll
        for (int kk = 0; kk < 2; kk++) {
            int kt = ktlo + kk;
            uint4 ah[2], al[2];
            #pragma unroll
            for (int m = 0; m < 2; m++) {
                int base = buf*A_BUF + ((kt*8 + wm*2 + m)*32 + lane)*4;
                ah[m] = *(const uint4*)&As[base];
                al[m] = *(const uint4*)&As[base + 4096];
            }
            #pragma unroll
            for (int n = 0; n < 8; n++) {
                int bbase = buf*B_BUF + ((kt*32 + wn*8 + n)*32 + lane)*2;
                uint2 bh = *(const uint2*)&Bs[bbase];
                uint2 bl = *(const uint2*)&Bs[bbase + 8192];
                #pragma unroll
                for (int m = 0; m < 2; m++) {
                    mma_tf32(acc[m][n], ah[m].x, ah[m].y, ah[m].z, ah[m].w, bh.x, bh.y);
                    mma_tf32(acc[m][n], ah[m].x, ah[m].y, ah[m].z, ah[m].w, bl.x, bl.y);
                    mma_tf32(acc[m][n], al[m].x, al[m].y, al[m].z, al[m].w, bh.x, bh.y);
                }
            }
        }
    };

    // --- prologue: stage chunk 0 into buffer 0 ---
    issue_b(0, 0);
    CP_COMMIT();
    ld_a(0, 0); cvt_a(0, 0);
    ld_a(0, 1); cvt_a(0, 1);
    CP_WAIT0();
    __syncthreads();

    // --- main pipeline: cvt of next chunk interleaved between kt halves ---
    for (int ch = 0; ch < NCHUNK; ch++) {
        int buf = ch & 1, nbuf = buf ^ 1;
        bool more = (ch + 1 < NCHUNK);
        if (more) {
            issue_b(ch + 1, nbuf);
            CP_COMMIT();
            ld_a(ch + 1, 0);
        }
        compute(buf, 0);
        if (more) {
            cvt_a(nbuf, 0);
            ld_a(ch + 1, 1);
        }
        compute(buf, 2);
        if (more) {
            cvt_a(nbuf, 1);
            CP_WAIT0();
        }
        __syncthreads();
    }

    // --- epilogue: per-thread min over its 16 codes for each of 4 pixels ---
    #pragma unroll
    for (int m = 0; m < 2; m++) {
        unsigned long long b0 = ~0ull, b1 = ~0ull;
        #pragma unroll
        for (int n = 0; n < 8; n++) {
            int j0 = wn*64 + n*8 + tig*2;
            #pragma unroll
            for (int q = 0; q < 2; q++) {
                float s_lo = ee2_s[j0+q] - 2.f*acc[m][n][q];     // pixel row g
                float s_hi = ee2_s[j0+q] - 2.f*acc[m][n][q+2];   // pixel row g+8
                unsigned u0 = __float_as_uint(s_lo);
                u0 = (u0 & 0x80000000u) ? ~u0 : (u0 | 0x80000000u);
                unsigned long long k0 = ((unsigned long long)u0 << 32) | (unsigned)(j0+q);
                b0 = (k0 < b0) ? k0 : b0;
                unsigned u1 = __float_as_uint(s_hi);
                u1 = (u1 & 0x80000000u) ? ~u1 : (u1 | 0x80000000u);
                unsigned long long k1 = ((unsigned long long)u1 << 32) | (unsigned)(j0+q);
                b1 = (k1 < b1) ? k1 : b1;
            }
        }
        int prow = wm*32 + m*16 + g;
        atomicMin(&sKey[prow], b0);
        atomicMin(&sKey[prow + 8], b1);
    }
    __syncthreads();

    float dmin = 0.f;
    if (t < 128) {
        unsigned long long k = sKey[t];
        int j = (int)(k & 0xFFFFFFFFu);
        unsigned u = (unsigned)(k >> 32);
        unsigned fb = (u & 0x80000000u) ? (u & 0x7FFFFFFFu) : ~u;
        dmin = __uint_as_float(fb);
        int n = cta*128 + t;
        g_idx[n] = j;
        atomicAdd(&g_counts[j], 1);
        out[IDX_OFF + n] = (float)j;
    }

    redf[t] = zsq + dmin;
    __syncthreads();
    for (int st = 256; st > 0; st >>= 1) { if (t < st) redf[t] += redf[t+st]; __syncthreads(); }
    if (t == 0) atomicAdd(&g_loss_sum, redf[0]);
}

// ---------------------------------------------------------------------------
// Kernel 3: gather-scatter + fused finalize (block 0).
// out[b,o,h,w] = code_out[o][idx[b,h,w]].
// ---------------------------------------------------------------------------
__global__ void __launch_bounds__(256) k_scatter(float* __restrict__ out)
{
    int bid = blockIdx.x;
    int b  = bid >> 5, oc = bid & 31;
    __shared__ int   idx_s[1024];
    __shared__ float ct[32*256];
    __shared__ float fred[256];
    int t = threadIdx.x;

    if (bid == 0) {   // fused finalize: loss + perplexity
        float em = (float)g_counts[t] / (float)NPIX;
        fred[t] = em * logf(em + 1e-10f);
        __syncthreads();
        for (int st = 128; st > 0; st >>= 1) { if (t < st) fred[t] += fred[t+st]; __syncthreads(); }
        if (t == 0) {
            out[LOSS_OFF] = 1.25f * g_loss_sum / (float)OUT_ELEMS;
            out[PERP_OFF] = expf(-fred[0]);
        }
    }

    #pragma unroll
    for (int r = 0; r < 4; r++) idx_s[t + 256*r] = g_idx[b*1024 + t + 256*r];
    const float4* src = (const float4*)(g_code_out + (size_t)oc*32*NE);
    float4* dst = (float4*)ct;
    #pragma unroll
    for (int r = 0; r < 8; r++) dst[t + 256*r] = src[t + 256*r];
    __syncthreads();
    int warp = t >> 5, lane = t & 31;
    float* ob = out + (size_t)b*(CC*HH*WW) + (size_t)oc*32*(HH*WW);
    #pragma unroll
    for (int q = 0; q < 4; q++) {
        int o = warp*4 + q;
        const float* crow = &ct[o*NE];
        #pragma unroll
        for (int p0 = 0; p0 < 1024; p0 += 128) {
            int4 j4 = *(const int4*)&idx_s[p0 + lane*4];
            float4 v;
            v.x = crow[j4.x]; v.y = crow[j4.y]; v.z = crow[j4.z]; v.w = crow[j4.w];
            *(float4*)&ob[(size_t)o*(HH*WW) + p0 + lane*4] = v;
        }
    }
}

// ---------------------------------------------------------------------------
// Launch: fork k_codeout onto a side stream, join before k_scatter.
// ---------------------------------------------------------------------------
extern "C" void kernel_launch(void* const* d_in, const int* in_sizes, int n_in,
                              void* d_out, int out_size) {
    const float* z      = (const float*)d_in[0];
    const float* emb    = (const float*)d_in[1];
    const float* conv_w = (const float*)d_in[2];
    const float* conv_b = (const float*)d_in[3];
    float* out = (float*)d_out;

    static cudaStream_t s_side = 0;
    static cudaEvent_t  ev_fork = 0, ev_join = 0;
    if (s_side == 0) {
        cudaStreamCreateWithFlags(&s_side, cudaStreamNonBlocking);
        cudaEventCreateWithFlags(&ev_fork, cudaEventDisableTiming);
        cudaEventCreateWithFlags(&ev_join, cudaEventDisableTiming);
        cudaFuncSetAttribute(k_argmin_tc, cudaFuncAttributeMaxDynamicSharedMemorySize, DYN_SMEM);
    }

    cudaEventRecord(ev_fork, 0);
    cudaStreamWaitEvent(s_side, ev_fork, 0);

    k_codeout<<<dim3(CC/64, NE/64), 256, 0, s_side>>>(emb, conv_w, conv_b);
    cudaEventRecord(ev_join, s_side);

    k_prep<<<NE, 256>>>(emb);
    k_argmin_tc<<<NPIX/128, 512, DYN_SMEM>>>(z, out);

    cudaStreamWaitEvent(0, ev_join, 0);
    k_scatter<<<BB*HH, 256>>>(out);
}